// round 5
// baseline (speedup 1.0000x reference)
#include <cuda_runtime.h>
#include <cuda_fp16.h>
#include <math.h>
#include <cstdint>

#define D_MODEL 1280
#define NHEADS  16
#define HDIM    80
#define S_MAX   4096

// ---------------- scratch (device globals; no allocation allowed) ----------
__device__ float g_qkv[S_MAX * 3 * D_MODEL];
__device__ float g_q[NHEADS * S_MAX * HDIM];
__device__ float g_k[NHEADS * S_MAX * HDIM];
__device__ float g_v[NHEADS * S_MAX * HDIM];
__device__ float g_attn[S_MAX * D_MODEL];
__device__ float g_wqkv_t[3 * D_MODEL * D_MODEL];   // (3D, D) K-major
__device__ float g_wproj_t[D_MODEL * D_MODEL];      // (D, D) K-major

// ======================= helpers ===========================================
__device__ __forceinline__ uint32_t smem_u32(const void* p) {
    uint32_t a;
    asm("{ .reg .u64 t; cvta.to.shared.u64 t, %1; cvt.u32.u64 %0, t; }" : "=r"(a) : "l"(p));
    return a;
}
__device__ __forceinline__ void cp16(uint32_t dst, const void* src) {
    asm volatile("cp.async.cg.shared.global [%0], [%1], 16;" :: "r"(dst), "l"(src));
}
#define CP_COMMIT() asm volatile("cp.async.commit_group;" ::: "memory")
#define CP_WAIT(n)  asm volatile("cp.async.wait_group %0;" :: "n"(n) : "memory")

__device__ __forceinline__ uint32_t f2tf32(float x) {
    uint32_t r;
    asm("cvt.rna.tf32.f32 %0, %1;" : "=r"(r) : "f"(x));
    return r;
}

__device__ __forceinline__ void mma_tf32(float* c, const uint32_t* a, const uint32_t* b) {
    asm volatile(
        "mma.sync.aligned.m16n8k8.row.col.f32.tf32.tf32.f32 "
        "{%0,%1,%2,%3}, {%4,%5,%6,%7}, {%8,%9}, {%0,%1,%2,%3};"
        : "+f"(c[0]), "+f"(c[1]), "+f"(c[2]), "+f"(c[3])
        : "r"(a[0]), "r"(a[1]), "r"(a[2]), "r"(a[3]), "r"(b[0]), "r"(b[1]));
}

__device__ __forceinline__ void mma_f16(float* c, const uint32_t* a, const uint32_t* b) {
    asm volatile(
        "mma.sync.aligned.m16n8k16.row.col.f32.f16.f16.f32 "
        "{%0,%1,%2,%3}, {%4,%5,%6,%7}, {%8,%9}, {%0,%1,%2,%3};"
        : "+f"(c[0]), "+f"(c[1]), "+f"(c[2]), "+f"(c[3])
        : "r"(a[0]), "r"(a[1]), "r"(a[2]), "r"(a[3]), "r"(b[0]), "r"(b[1]));
}

__device__ __forceinline__ uint32_t pack_h2(float lo, float hi) {
    __half2 h = __floats2half2_rn(lo, hi);
    return *reinterpret_cast<uint32_t*>(&h);
}

// ======================= transpose (K,N) -> (N,K) ==========================
__global__ void transpose_kernel(const float* __restrict__ in, float* __restrict__ out,
                                 int K, int N) {
    __shared__ float tile[32][33];
    const int k0 = blockIdx.y * 32, n0 = blockIdx.x * 32;
    const int tx = threadIdx.x, ty = threadIdx.y;
    #pragma unroll
    for (int i = ty; i < 32; i += 8)
        tile[i][tx] = in[(size_t)(k0 + i) * N + n0 + tx];
    __syncthreads();
    #pragma unroll
    for (int i = ty; i < 32; i += 8)
        out[(size_t)(n0 + i) * K + k0 + tx] = tile[tx][i];
}

// ======================= tf32 mma.sync GEMM ================================
#define GSTR 36
#define GEMM_SMEM (2 * 2 * 128 * GSTR * 4)

__global__ __launch_bounds__(256, 1)
void gemm_tf32(const float* __restrict__ A, const float* __restrict__ Bt,
               const float* __restrict__ bias, float* __restrict__ C,
               int M, int N, int K)
{
    extern __shared__ float sm[];
    const int tid  = threadIdx.x;
    const int warp = tid >> 5, lane = tid & 31;
    const int gid  = lane >> 2, tid4 = lane & 3;
    const int wm0  = (warp & 3) * 32;
    const int wn0  = (warp >> 2) * 64;
    const int bx = blockIdx.x, by = blockIdx.y;

    const float* Ablk = A  + (size_t)by * 128 * K;
    const float* Bblk = Bt + (size_t)bx * 128 * K;
    const int NS = K / 32;
    const uint32_t sbase = smem_u32(sm);

    auto load_stage = [&](int b, int ks) {
        #pragma unroll
        for (int i = 0; i < 8; i++) {
            const int id  = tid + i * 256;
            const int isB = id >> 10;
            const int row = (id >> 3) & 127;
            const int c16 = id & 7;
            const float* src = (isB ? Bblk : Ablk) + (size_t)row * K + ks * 32 + c16 * 4;
            const uint32_t dst = sbase +
                (uint32_t)(b * (2 * 128 * GSTR) + isB * (128 * GSTR) + row * GSTR + c16 * 4) * 4u;
            cp16(dst, src);
        }
        CP_COMMIT();
    };

    float acc[2][8][4];
    #pragma unroll
    for (int mt = 0; mt < 2; mt++)
        #pragma unroll
        for (int nt = 0; nt < 8; nt++)
            #pragma unroll
            for (int r = 0; r < 4; r++) acc[mt][nt][r] = 0.f;

    load_stage(0, 0);
    for (int ks = 0; ks < NS; ks++) {
        const int b = ks & 1;
        if (ks + 1 < NS) { load_stage(1 - b, ks + 1); CP_WAIT(1); }
        else             { CP_WAIT(0); }
        __syncthreads();

        const float* As = sm + b * (2 * 128 * GSTR);
        const float* Bs = As + 128 * GSTR;

        #pragma unroll
        for (int kk = 0; kk < 4; kk++) {
            const int k0 = kk * 8;
            uint32_t af[2][4], bf[8][2];
            #pragma unroll
            for (int mt = 0; mt < 2; mt++) {
                const int r = (wm0 + mt * 16 + gid) * GSTR;
                af[mt][0] = f2tf32(As[r + k0 + tid4]);
                af[mt][1] = f2tf32(As[r + 8 * GSTR + k0 + tid4]);
                af[mt][2] = f2tf32(As[r + k0 + tid4 + 4]);
                af[mt][3] = f2tf32(As[r + 8 * GSTR + k0 + tid4 + 4]);
            }
            #pragma unroll
            for (int nt = 0; nt < 8; nt++) {
                const int r = (wn0 + nt * 8 + gid) * GSTR;
                bf[nt][0] = f2tf32(Bs[r + k0 + tid4]);
                bf[nt][1] = f2tf32(Bs[r + k0 + tid4 + 4]);
            }
            #pragma unroll
            for (int mt = 0; mt < 2; mt++)
                #pragma unroll
                for (int nt = 0; nt < 8; nt++)
                    mma_tf32(acc[mt][nt], af[mt], bf[nt]);
        }
        __syncthreads();
    }

    float* Cs = sm;
    #pragma unroll
    for (int mt = 0; mt < 2; mt++)
        #pragma unroll
        for (int nt = 0; nt < 8; nt++) {
            const int row = wm0 + mt * 16 + gid;
            const int col = wn0 + nt * 8 + tid4 * 2;
            Cs[row * 132 + col]           = acc[mt][nt][0];
            Cs[row * 132 + col + 1]       = acc[mt][nt][1];
            Cs[(row + 8) * 132 + col]     = acc[mt][nt][2];
            Cs[(row + 8) * 132 + col + 1] = acc[mt][nt][3];
        }
    __syncthreads();
    #pragma unroll
    for (int it = 0; it < 16; it++) {
        const int id  = tid + it * 256;
        const int row = id >> 5;
        const int c4  = (id & 31) * 4;
        float4 v = *reinterpret_cast<const float4*>(&Cs[row * 132 + c4]);
        const int gc = bx * 128 + c4;
        v.x += bias[gc + 0]; v.y += bias[gc + 1]; v.z += bias[gc + 2]; v.w += bias[gc + 3];
        *reinterpret_cast<float4*>(&C[(size_t)(by * 128 + row) * N + gc]) = v;
    }
}

// ======================= RoPE + scatter to (H, S, hd) ======================
__global__ void rope_scatter(const float* __restrict__ qkv,
                             const float* __restrict__ freqs,
                             float* __restrict__ Q, float* __restrict__ K,
                             float* __restrict__ V, int S)
{
    const int s = blockIdx.x;
    const float* base = qkv + (size_t)s * (3 * D_MODEL);
    for (int idx = threadIdx.x; idx < NHEADS * HDIM; idx += blockDim.x) {
        const int h = idx / HDIM;
        const int d = idx % HDIM;
        const int dd = (d < 40) ? d : d - 40;
        const float f  = freqs[(size_t)s * 40 + dd];
        const float cs = cosf(f), sn = sinf(f);
        const float q1 = base[h * HDIM + dd];
        const float q2 = base[h * HDIM + dd + 40];
        const float k1 = base[D_MODEL + h * HDIM + dd];
        const float k2 = base[D_MODEL + h * HDIM + dd + 40];
        const float qo = (d < 40) ? (q1 * cs - q2 * sn) : (q1 * sn + q2 * cs);
        const float ko = (d < 40) ? (k1 * cs - k2 * sn) : (k1 * sn + k2 * cs);
        const size_t o = ((size_t)h * S + s) * HDIM + d;
        Q[o] = qo;
        K[o] = ko;
        V[o] = base[2 * D_MODEL + h * HDIM + d];
    }
}

// ======================= fp16-split tensor-core attention ==================
// CTA = (q-tile 128, head). 8 warps x 16 q-rows. KV tile = 64.
// QK^T: 3-MMA hi/lo fp16 split (error = tf32 split).  PV: V-side split, P in
// registers (accumulator layout == fp16 A-frag layout, just cvt+pack).
#define QSTR 88   // halves per Q/K row (80 data + 8 pad) -> conflict-free frags
#define VSTR 72   // halves per Vt row (64 keys + 8 pad)
#define ATC_SMEM ((2 * 128 * QSTR + 2 * 64 * QSTR + 2 * 80 * VSTR) * 2)  // 90624 B

__global__ __launch_bounds__(256, 2)
void attn_tc(const float* __restrict__ Qg, const float* __restrict__ Kg,
             const float* __restrict__ Vg, const int* __restrict__ cu,
             int n_seg, float* __restrict__ out, int S)
{
    extern __shared__ __half sh[];
    __half* Qh = sh;
    __half* Ql = Qh + 128 * QSTR;
    __half* Kh = Ql + 128 * QSTR;
    __half* Kl = Kh + 64 * QSTR;
    __half* Vh = Kl + 64 * QSTR;   // transposed [d][key]
    __half* Vl = Vh + 80 * VSTR;

    const int tid  = threadIdx.x;
    const int warp = tid >> 5, lane = tid & 31;
    const int gid  = lane >> 2, t4 = lane & 3;
    const int wq   = warp * 16;
    const int h    = blockIdx.y;
    const int q0   = blockIdx.x * 128;

    int start = 0, end = S;
    for (int i = 0; i < n_seg; i++) {
        int a = cu[i], b = cu[i + 1];
        if (a <= q0 && q0 < b) { start = a; end = b; }
    }

    const float scale = 0.11180339887498949f;   // 1/sqrt(80)

    // ---- load Q: scale + fp16 hi/lo split ----
    {
        const int r  = tid >> 1;
        const int cb = (tid & 1) * 40;
        const bool mv = (q0 + r) < end;
        const float* Qrow = Qg + ((size_t)h * S + q0 + r) * HDIM + cb;
        #pragma unroll
        for (int i = 0; i < 10; i++) {
            float4 v = mv ? *reinterpret_cast<const float4*>(Qrow + i * 4)
                          : make_float4(0.f, 0.f, 0.f, 0.f);
            const float* vp = &v.x;
            #pragma unroll
            for (int j = 0; j < 4; j++) {
                const float x = vp[j] * scale;
                const __half hi = __float2half_rn(x);
                Qh[r * QSTR + cb + i * 4 + j] = hi;
                Ql[r * QSTR + cb + i * 4 + j] = __float2half_rn(x - __half2float(hi));
            }
        }
    }

    float acc_o[10][4];
    #pragma unroll
    for (int n = 0; n < 10; n++)
        #pragma unroll
        for (int r = 0; r < 4; r++) acc_o[n][r] = 0.f;
    float m0 = -INFINITY, m1 = -INFINITY, l0 = 0.f, l1 = 0.f;

    const int nkt = (end - start + 63) / 64;
    for (int t = 0; t < nkt; t++) {
        const int k0 = start + t * 64;
        __syncthreads();   // previous tile's consumers done

        // ---- load K (row-major split) and V (transposed split) ----
        {
            const int r  = tid >> 2;          // key 0..63
            const int cb = (tid & 3) * 20;    // d chunk
            const bool mv = (k0 + r) < end;
            const float* Krow = Kg + ((size_t)h * S + k0 + r) * HDIM + cb;
            const float* Vrow = Vg + ((size_t)h * S + k0 + r) * HDIM + cb;
            #pragma unroll
            for (int i = 0; i < 5; i++) {
                float4 kk = mv ? *reinterpret_cast<const float4*>(Krow + i * 4)
                               : make_float4(0.f, 0.f, 0.f, 0.f);
                float4 vv = mv ? *reinterpret_cast<const float4*>(Vrow + i * 4)
                               : make_float4(0.f, 0.f, 0.f, 0.f);
                const float* kp = &kk.x;
                const float* vp = &vv.x;
                #pragma unroll
                for (int j = 0; j < 4; j++) {
                    const int d = cb + i * 4 + j;
                    const __half khi = __float2half_rn(kp[j]);
                    Kh[r * QSTR + d] = khi;
                    Kl[r * QSTR + d] = __float2half_rn(kp[j] - __half2float(khi));
                    const __half vhi = __float2half_rn(vp[j]);
                    Vh[d * VSTR + r] = vhi;
                    Vl[d * VSTR + r] = __float2half_rn(vp[j] - __half2float(vhi));
                }
            }
        }
        __syncthreads();

        // ---- QK^T: 5 k16-blocks, 3-MMA split ----
        float acc_s[8][4];
        #pragma unroll
        for (int n = 0; n < 8; n++)
            #pragma unroll
            for (int r = 0; r < 4; r++) acc_s[n][r] = 0.f;

        #pragma unroll
        for (int kk = 0; kk < 5; kk++) {
            const int kb = kk * 16 + 2 * t4;
            uint32_t ah[4], al[4];
            ah[0] = *reinterpret_cast<const uint32_t*>(&Qh[(wq + gid)     * QSTR + kb]);
            ah[1] = *reinterpret_cast<const uint32_t*>(&Qh[(wq + gid + 8) * QSTR + kb]);
            ah[2] = *reinterpret_cast<const uint32_t*>(&Qh[(wq + gid)     * QSTR + kb + 8]);
            ah[3] = *reinterpret_cast<const uint32_t*>(&Qh[(wq + gid + 8) * QSTR + kb + 8]);
            al[0] = *reinterpret_cast<const uint32_t*>(&Ql[(wq + gid)     * QSTR + kb]);
            al[1] = *reinterpret_cast<const uint32_t*>(&Ql[(wq + gid + 8) * QSTR + kb]);
            al[2] = *reinterpret_cast<const uint32_t*>(&Ql[(wq + gid)     * QSTR + kb + 8]);
            al[3] = *reinterpret_cast<const uint32_t*>(&Ql[(wq + gid + 8) * QSTR + kb + 8]);
            #pragma unroll
            for (int nt = 0; nt < 8; nt++) {
                uint32_t bh[2], bl[2];
                bh[0] = *reinterpret_cast<const uint32_t*>(&Kh[(nt * 8 + gid) * QSTR + kb]);
                bh[1] = *reinterpret_cast<const uint32_t*>(&Kh[(nt * 8 + gid) * QSTR + kb + 8]);
                bl[0] = *reinterpret_cast<const uint32_t*>(&Kl[(nt * 8 + gid) * QSTR + kb]);
                bl[1] = *reinterpret_cast<const uint32_t*>(&Kl[(nt * 8 + gid) * QSTR + kb + 8]);
                mma_f16(acc_s[nt], ah, bh);
                mma_f16(acc_s[nt], al, bh);
                mma_f16(acc_s[nt], ah, bl);
            }
        }

        // ---- mask + online softmax (rows warp-local) ----
        const int nv = end - k0;
        float mt0 = -INFINITY, mt1 = -INFINITY;
        #pragma unroll
        for (int nt = 0; nt < 8; nt++) {
            #pragma unroll
            for (int j = 0; j < 2; j++) {
                const int c = nt * 8 + 2 * t4 + j;
                if (c >= nv) { acc_s[nt][j] = -1e30f; acc_s[nt][2 + j] = -1e30f; }
                mt0 = fmaxf(mt0, acc_s[nt][j]);
                mt1 = fmaxf(mt1, acc_s[nt][2 + j]);
            }
        }
        mt0 = fmaxf(mt0, __shfl_xor_sync(0xffffffffu, mt0, 1));
        mt0 = fmaxf(mt0, __shfl_xor_sync(0xffffffffu, mt0, 2));
        mt1 = fmaxf(mt1, __shfl_xor_sync(0xffffffffu, mt1, 1));
        mt1 = fmaxf(mt1, __shfl_xor_sync(0xffffffffu, mt1, 2));

        const float mn0 = fmaxf(m0, mt0), mn1 = fmaxf(m1, mt1);
        const float al0 = __expf(m0 - mn0), al1 = __expf(m1 - mn1);
        m0 = mn0; m1 = mn1;

        float rs0 = 0.f, rs1 = 0.f;
        #pragma unroll
        for (int nt = 0; nt < 8; nt++) {
            #pragma unroll
            for (int j = 0; j < 2; j++) {
                const float p0 = __expf(acc_s[nt][j]     - m0);
                const float p1 = __expf(acc_s[nt][2 + j] - m1);
                acc_s[nt][j]     = p0;
                acc_s[nt][2 + j] = p1;
                rs0 += p0; rs1 += p1;
            }
        }
        rs0 += __shfl_xor_sync(0xffffffffu, rs0, 1);
        rs0 += __shfl_xor_sync(0xffffffffu, rs0, 2);
        rs1 += __shfl_xor_sync(0xffffffffu, rs1, 1);
        rs1 += __shfl_xor_sync(0xffffffffu, rs1, 2);
        l0 = l0 * al0 + rs0;
        l1 = l1 * al1 + rs1;

        #pragma unroll
        for (int n = 0; n < 10; n++) {
            acc_o[n][0] *= al0; acc_o[n][1] *= al0;
            acc_o[n][2] *= al1; acc_o[n][3] *= al1;
        }

        // ---- pack P into fp16 A-fragments (registers only) ----
        uint32_t pk[4][4];   // [kk16-block][frag reg]
        #pragma unroll
        for (int kk = 0; kk < 4; kk++) {
            pk[kk][0] = pack_h2(acc_s[2 * kk][0],     acc_s[2 * kk][1]);
            pk[kk][1] = pack_h2(acc_s[2 * kk][2],     acc_s[2 * kk][3]);
            pk[kk][2] = pack_h2(acc_s[2 * kk + 1][0], acc_s[2 * kk + 1][1]);
            pk[kk][3] = pack_h2(acc_s[2 * kk + 1][2], acc_s[2 * kk + 1][3]);
        }

        // ---- PV: 4 k16-blocks (64 keys), V-split 2 MMAs ----
        #pragma unroll
        for (int kk = 0; kk < 4; kk++) {
            const int kb = kk * 16 + 2 * t4;
            #pragma unroll
            for (int nt = 0; nt < 10; nt++) {
                uint32_t bh[2], bl[2];
                bh[0] = *reinterpret_cast<const uint32_t*>(&Vh[(nt * 8 + gid) * VSTR + kb]);
                bh[1] = *reinterpret_cast<const uint32_t*>(&Vh[(nt * 8 + gid) * VSTR + kb + 8]);
                bl[0] = *reinterpret_cast<const uint32_t*>(&Vl[(nt * 8 + gid) * VSTR + kb]);
                bl[1] = *reinterpret_cast<const uint32_t*>(&Vl[(nt * 8 + gid) * VSTR + kb + 8]);
                mma_f16(acc_o[nt], pk[kk], bh);
                mma_f16(acc_o[nt], pk[kk], bl);
            }
        }
    }

    // ---- epilogue ----
    const float inv0 = 1.f / l0, inv1 = 1.f / l1;
    const int r0 = q0 + wq + gid, r1 = r0 + 8;
    #pragma unroll
    for (int nt = 0; nt < 10; nt++) {
        const int col = h * HDIM + nt * 8 + 2 * t4;
        if (r0 < end) {
            float2 v = make_float2(acc_o[nt][0] * inv0, acc_o[nt][1] * inv0);
            *reinterpret_cast<float2*>(&out[(size_t)r0 * D_MODEL + col]) = v;
        }
        if (r1 < end) {
            float2 v = make_float2(acc_o[nt][2] * inv1, acc_o[nt][3] * inv1);
            *reinterpret_cast<float2*>(&out[(size_t)r1 * D_MODEL + col]) = v;
        }
    }
}

// ======================= launch ============================================
extern "C" void kernel_launch(void* const* d_in, const int* in_sizes, int n_in,
                              void* d_out, int out_size)
{
    const float* hidden = (const float*)d_in[0];
    const int*   cu     = (const int*)  d_in[1];
    const float* rope   = (const float*)d_in[2];
    const float* w_qkv  = (const float*)d_in[3];
    const float* b_qkv  = (const float*)d_in[4];
    const float* w_proj = (const float*)d_in[5];
    const float* b_proj = (const float*)d_in[6];
    float* out = (float*)d_out;

    const int S     = in_sizes[0] / D_MODEL;
    const int n_seg = in_sizes[1] - 1;

    float *qkv_p, *q_p, *k_p, *v_p, *attn_p, *wqkv_t, *wproj_t;
    cudaGetSymbolAddress((void**)&qkv_p,   g_qkv);
    cudaGetSymbolAddress((void**)&q_p,     g_q);
    cudaGetSymbolAddress((void**)&k_p,     g_k);
    cudaGetSymbolAddress((void**)&v_p,     g_v);
    cudaGetSymbolAddress((void**)&attn_p,  g_attn);
    cudaGetSymbolAddress((void**)&wqkv_t,  g_wqkv_t);
    cudaGetSymbolAddress((void**)&wproj_t, g_wproj_t);

    cudaFuncSetAttribute(gemm_tf32, cudaFuncAttributeMaxDynamicSharedMemorySize, GEMM_SMEM);
    cudaFuncSetAttribute(attn_tc,   cudaFuncAttributeMaxDynamicSharedMemorySize, ATC_SMEM);

    // 0) transpose weights to K-major
    {
        dim3 blk(32, 8);
        transpose_kernel<<<dim3(3 * D_MODEL / 32, D_MODEL / 32), blk>>>(w_qkv, wqkv_t, D_MODEL, 3 * D_MODEL);
        transpose_kernel<<<dim3(D_MODEL / 32, D_MODEL / 32), blk>>>(w_proj, wproj_t, D_MODEL, D_MODEL);
    }

    // 1) QKV projection (tf32 mma.sync)
    gemm_tf32<<<dim3(3 * D_MODEL / 128, S / 128), 256, GEMM_SMEM>>>(
        hidden, wqkv_t, b_qkv, qkv_p, S, 3 * D_MODEL, D_MODEL);

    // 2) RoPE + scatter
    rope_scatter<<<S, 256>>>(qkv_p, rope, q_p, k_p, v_p, S);

    // 3) block-diagonal attention (fp16-split tensor cores)
    attn_tc<<<dim3(S / 128, NHEADS), 256, ATC_SMEM>>>(q_p, k_p, v_p, cu, n_seg, attn_p, S);

    // 4) output projection (tf32 mma.sync)
    gemm_tf32<<<dim3(D_MODEL / 128, S / 128), 256, GEMM_SMEM>>>(
        attn_p, wproj_t, b_proj, out, S, D_MODEL, D_MODEL);
}

// round 6
// speedup vs baseline: 1.5143x; 1.5143x over previous
#include <cuda_runtime.h>
#include <cuda_fp16.h>
#include <math.h>
#include <cstdint>

#define D_MODEL 1280
#define NHEADS  16
#define HDIM    80
#define S_MAX   4096

// ---------------- scratch (device globals; no allocation allowed) ----------
__device__ float g_qkv[S_MAX * 3 * D_MODEL];
__device__ float g_attn[S_MAX * D_MODEL];
__device__ float g_wqkv_t[3 * D_MODEL * D_MODEL];   // (3D, D) K-major
__device__ float g_wproj_t[D_MODEL * D_MODEL];      // (D, D) K-major
// fp16 hi/lo split tensors
__device__ __half g_qh[NHEADS * S_MAX * HDIM];      // (H,S,80)  scaled
__device__ __half g_ql[NHEADS * S_MAX * HDIM];
__device__ __half g_kh[NHEADS * S_MAX * HDIM];      // (H,S,80)
__device__ __half g_kl[NHEADS * S_MAX * HDIM];
__device__ __half g_vh[NHEADS * HDIM * S_MAX];      // (H,80,S)  transposed
__device__ __half g_vl[NHEADS * HDIM * S_MAX];

// ======================= helpers ===========================================
__device__ __forceinline__ uint32_t smem_u32(const void* p) {
    uint32_t a;
    asm("{ .reg .u64 t; cvta.to.shared.u64 t, %1; cvt.u32.u64 %0, t; }" : "=r"(a) : "l"(p));
    return a;
}
__device__ __forceinline__ void cp16(uint32_t dst, const void* src) {
    asm volatile("cp.async.cg.shared.global [%0], [%1], 16;" :: "r"(dst), "l"(src));
}
#define CP_COMMIT() asm volatile("cp.async.commit_group;" ::: "memory")
#define CP_WAIT(n)  asm volatile("cp.async.wait_group %0;" :: "n"(n) : "memory")

__device__ __forceinline__ uint32_t f2tf32(float x) {
    uint32_t r;
    asm("cvt.rna.tf32.f32 %0, %1;" : "=r"(r) : "f"(x));
    return r;
}
__device__ __forceinline__ void mma_tf32(float* c, const uint32_t* a, const uint32_t* b) {
    asm volatile(
        "mma.sync.aligned.m16n8k8.row.col.f32.tf32.tf32.f32 "
        "{%0,%1,%2,%3}, {%4,%5,%6,%7}, {%8,%9}, {%0,%1,%2,%3};"
        : "+f"(c[0]), "+f"(c[1]), "+f"(c[2]), "+f"(c[3])
        : "r"(a[0]), "r"(a[1]), "r"(a[2]), "r"(a[3]), "r"(b[0]), "r"(b[1]));
}
__device__ __forceinline__ void mma_f16(float* c, const uint32_t* a, const uint32_t* b) {
    asm volatile(
        "mma.sync.aligned.m16n8k16.row.col.f32.f16.f16.f32 "
        "{%0,%1,%2,%3}, {%4,%5,%6,%7}, {%8,%9}, {%0,%1,%2,%3};"
        : "+f"(c[0]), "+f"(c[1]), "+f"(c[2]), "+f"(c[3])
        : "r"(a[0]), "r"(a[1]), "r"(a[2]), "r"(a[3]), "r"(b[0]), "r"(b[1]));
}
__device__ __forceinline__ void ldsm4(uint32_t* r, uint32_t addr) {
    asm volatile("ldmatrix.sync.aligned.m8n8.x4.shared.b16 {%0,%1,%2,%3}, [%4];"
        : "=r"(r[0]), "=r"(r[1]), "=r"(r[2]), "=r"(r[3]) : "r"(addr));
}
__device__ __forceinline__ uint32_t pack_h2(float lo, float hi) {
    __half2 h = __floats2half2_rn(lo, hi);
    return *reinterpret_cast<uint32_t*>(&h);
}

// ======================= transpose (K,N) -> (N,K) ==========================
__global__ void transpose_kernel(const float* __restrict__ in, float* __restrict__ out,
                                 int K, int N) {
    __shared__ float tile[32][33];
    const int k0 = blockIdx.y * 32, n0 = blockIdx.x * 32;
    const int tx = threadIdx.x, ty = threadIdx.y;
    #pragma unroll
    for (int i = ty; i < 32; i += 8)
        tile[i][tx] = in[(size_t)(k0 + i) * N + n0 + tx];
    __syncthreads();
    #pragma unroll
    for (int i = ty; i < 32; i += 8)
        out[(size_t)(n0 + i) * K + k0 + tx] = tile[tx][i];
}

// ======================= tf32 mma.sync GEMM ================================
#define GSTR 36
#define GEMM_SMEM (2 * 2 * 128 * GSTR * 4)

__global__ __launch_bounds__(256, 1)
void gemm_tf32(const float* __restrict__ A, const float* __restrict__ Bt,
               const float* __restrict__ bias, float* __restrict__ C,
               int M, int N, int K)
{
    extern __shared__ float sm[];
    const int tid  = threadIdx.x;
    const int warp = tid >> 5, lane = tid & 31;
    const int gid  = lane >> 2, tid4 = lane & 3;
    const int wm0  = (warp & 3) * 32;
    const int wn0  = (warp >> 2) * 64;
    const int bx = blockIdx.x, by = blockIdx.y;

    const float* Ablk = A  + (size_t)by * 128 * K;
    const float* Bblk = Bt + (size_t)bx * 128 * K;
    const int NS = K / 32;
    const uint32_t sbase = smem_u32(sm);

    auto load_stage = [&](int b, int ks) {
        #pragma unroll
        for (int i = 0; i < 8; i++) {
            const int id  = tid + i * 256;
            const int isB = id >> 10;
            const int row = (id >> 3) & 127;
            const int c16 = id & 7;
            const float* src = (isB ? Bblk : Ablk) + (size_t)row * K + ks * 32 + c16 * 4;
            const uint32_t dst = sbase +
                (uint32_t)(b * (2 * 128 * GSTR) + isB * (128 * GSTR) + row * GSTR + c16 * 4) * 4u;
            cp16(dst, src);
        }
        CP_COMMIT();
    };

    float acc[2][8][4];
    #pragma unroll
    for (int mt = 0; mt < 2; mt++)
        #pragma unroll
        for (int nt = 0; nt < 8; nt++)
            #pragma unroll
            for (int r = 0; r < 4; r++) acc[mt][nt][r] = 0.f;

    load_stage(0, 0);
    for (int ks = 0; ks < NS; ks++) {
        const int b = ks & 1;
        if (ks + 1 < NS) { load_stage(1 - b, ks + 1); CP_WAIT(1); }
        else             { CP_WAIT(0); }
        __syncthreads();

        const float* As = sm + b * (2 * 128 * GSTR);
        const float* Bs = As + 128 * GSTR;

        #pragma unroll
        for (int kk = 0; kk < 4; kk++) {
            const int k0 = kk * 8;
            uint32_t af[2][4], bf[8][2];
            #pragma unroll
            for (int mt = 0; mt < 2; mt++) {
                const int r = (wm0 + mt * 16 + gid) * GSTR;
                af[mt][0] = f2tf32(As[r + k0 + tid4]);
                af[mt][1] = f2tf32(As[r + 8 * GSTR + k0 + tid4]);
                af[mt][2] = f2tf32(As[r + k0 + tid4 + 4]);
                af[mt][3] = f2tf32(As[r + 8 * GSTR + k0 + tid4 + 4]);
            }
            #pragma unroll
            for (int nt = 0; nt < 8; nt++) {
                const int r = (wn0 + nt * 8 + gid) * GSTR;
                bf[nt][0] = f2tf32(Bs[r + k0 + tid4]);
                bf[nt][1] = f2tf32(Bs[r + k0 + tid4 + 4]);
            }
            #pragma unroll
            for (int mt = 0; mt < 2; mt++)
                #pragma unroll
                for (int nt = 0; nt < 8; nt++)
                    mma_tf32(acc[mt][nt], af[mt], bf[nt]);
        }
        __syncthreads();
    }

    float* Cs = sm;
    #pragma unroll
    for (int mt = 0; mt < 2; mt++)
        #pragma unroll
        for (int nt = 0; nt < 8; nt++) {
            const int row = wm0 + mt * 16 + gid;
            const int col = wn0 + nt * 8 + tid4 * 2;
            Cs[row * 132 + col]           = acc[mt][nt][0];
            Cs[row * 132 + col + 1]       = acc[mt][nt][1];
            Cs[(row + 8) * 132 + col]     = acc[mt][nt][2];
            Cs[(row + 8) * 132 + col + 1] = acc[mt][nt][3];
        }
    __syncthreads();
    #pragma unroll
    for (int it = 0; it < 16; it++) {
        const int id  = tid + it * 256;
        const int row = id >> 5;
        const int c4  = (id & 31) * 4;
        float4 v = *reinterpret_cast<const float4*>(&Cs[row * 132 + c4]);
        const int gc = bx * 128 + c4;
        v.x += bias[gc + 0]; v.y += bias[gc + 1]; v.z += bias[gc + 2]; v.w += bias[gc + 3];
        *reinterpret_cast<float4*>(&C[(size_t)(by * 128 + row) * N + gc]) = v;
    }
}

// ======================= RoPE + split-scatter ==============================
// writes scaled Q (hi/lo) and K (hi/lo) in (H,S,80) fp16
__global__ void rope_scatter(const float* __restrict__ qkv,
                             const float* __restrict__ freqs,
                             __half* __restrict__ Qh, __half* __restrict__ Ql,
                             __half* __restrict__ Kh, __half* __restrict__ Kl,
                             int S)
{
    const int s = blockIdx.x;
    const float* base = qkv + (size_t)s * (3 * D_MODEL);
    const float scale = 0.11180339887498949f;   // 1/sqrt(80)
    for (int idx = threadIdx.x; idx < NHEADS * HDIM; idx += blockDim.x) {
        const int h = idx / HDIM;
        const int d = idx % HDIM;
        const int dd = (d < 40) ? d : d - 40;
        const float f  = freqs[(size_t)s * 40 + dd];
        const float cs = cosf(f), sn = sinf(f);
        const float q1 = base[h * HDIM + dd];
        const float q2 = base[h * HDIM + dd + 40];
        const float k1 = base[D_MODEL + h * HDIM + dd];
        const float k2 = base[D_MODEL + h * HDIM + dd + 40];
        float qo = (d < 40) ? (q1 * cs - q2 * sn) : (q1 * sn + q2 * cs);
        const float ko = (d < 40) ? (k1 * cs - k2 * sn) : (k1 * sn + k2 * cs);
        qo *= scale;
        const size_t o = ((size_t)h * S + s) * HDIM + d;
        const __half qhi = __float2half_rn(qo);
        Qh[o] = qhi;
        Ql[o] = __float2half_rn(qo - __half2float(qhi));
        const __half khi = __float2half_rn(ko);
        Kh[o] = khi;
        Kl[o] = __float2half_rn(ko - __half2float(khi));
    }
}

// ======================= V transpose + split ===============================
// (S, 3D) qkv -> Vh/Vl (H, 80, S) fp16
__global__ void vtrans(const float* __restrict__ qkv,
                       __half* __restrict__ Vh, __half* __restrict__ Vl, int S)
{
    __shared__ float tile[64][84];
    const int tid = threadIdx.x;
    const int h  = blockIdx.y;
    const int s0 = blockIdx.x * 64;

    // load 64 tokens x 80 dims
    {
        const int sl = tid >> 2;
        const int dc = (tid & 3) * 20;
        const float* src = qkv + (size_t)(s0 + sl) * (3 * D_MODEL) + 2 * D_MODEL + h * HDIM + dc;
        #pragma unroll
        for (int i = 0; i < 5; i++) {
            float4 v = *reinterpret_cast<const float4*>(src + i * 4);
            tile[sl][dc + i * 4 + 0] = v.x;
            tile[sl][dc + i * 4 + 1] = v.y;
            tile[sl][dc + i * 4 + 2] = v.z;
            tile[sl][dc + i * 4 + 3] = v.w;
        }
    }
    __syncthreads();

    if (tid < 160) {
        const int d  = tid >> 1;
        const int sh = (tid & 1) * 32;
        const size_t o = ((size_t)(h * HDIM + d)) * S + s0 + sh;
        #pragma unroll
        for (int j = 0; j < 16; j++) {
            const float v0 = tile[sh + 2 * j][d];
            const float v1 = tile[sh + 2 * j + 1][d];
            const __half h0 = __float2half_rn(v0);
            const __half h1 = __float2half_rn(v1);
            __half2 hi; hi.x = h0; hi.y = h1;
            __half2 lo;
            lo.x = __float2half_rn(v0 - __half2float(h0));
            lo.y = __float2half_rn(v1 - __half2float(h1));
            *reinterpret_cast<__half2*>(&Vh[o + 2 * j]) = hi;
            *reinterpret_cast<__half2*>(&Vl[o + 2 * j]) = lo;
        }
    }
}

// ======================= fp16-split tensor-core attention ==================
// CTA = (q-tile 128, head), 8 warps x 16 q-rows, KV tile 64, 2-stage cp.async.
#define QSTR 88   // halves (176B rows -> conflict-free ldmatrix)
#define VSTR 72   // halves (144B rows -> conflict-free)
#define ATT_Q  (128 * QSTR)
#define ATT_K  (64 * QSTR)
#define ATT_V  (80 * VSTR)
#define ATC_SMEM ((2 * ATT_Q + 4 * ATT_K + 4 * ATT_V) * 2)   // 136192 B

__global__ __launch_bounds__(256)
void attn_tc(const __half* __restrict__ gQh, const __half* __restrict__ gQl,
             const __half* __restrict__ gKh, const __half* __restrict__ gKl,
             const __half* __restrict__ gVh, const __half* __restrict__ gVl,
             const int* __restrict__ cu, int n_seg,
             float* __restrict__ out, int S)
{
    extern __shared__ __half sh[];
    __half* Qh = sh;
    __half* Ql = Qh + ATT_Q;
    __half* Kh = Ql + ATT_Q;           // [2][64*QSTR]
    __half* Kl = Kh + 2 * ATT_K;
    __half* Vh = Kl + 2 * ATT_K;       // [2][80*VSTR]
    __half* Vl = Vh + 2 * ATT_V;

    const uint32_t uQh = smem_u32(Qh), uQl = smem_u32(Ql);
    const uint32_t uKh = smem_u32(Kh), uKl = smem_u32(Kl);
    const uint32_t uVh = smem_u32(Vh), uVl = smem_u32(Vl);

    const int tid  = threadIdx.x;
    const int warp = tid >> 5, lane = tid & 31;
    const int gid  = lane >> 2, t4 = lane & 3;
    const int wq   = warp * 16;
    const int h    = blockIdx.y;
    const int q0   = blockIdx.x * 128;

    int start = 0, end = S;
    for (int i = 0; i < n_seg; i++) {
        int a = cu[i], b = cu[i + 1];
        if (a <= q0 && q0 < b) { start = a; end = b; }
    }

    // ---- Q load (cp.async): 10 chunks/thread ----
    {
        const int r  = tid >> 1;
        const int cb = (tid & 1) * 40;
        const int qr = min(q0 + r, S - 1);
        const size_t so = ((size_t)h * S + qr) * HDIM + cb;
        const uint32_t doff = (uint32_t)(r * QSTR + cb) * 2u;
        #pragma unroll
        for (int i = 0; i < 5; i++) {
            cp16(uQh + doff + i * 16, gQh + so + i * 8);
            cp16(uQl + doff + i * 16, gQl + so + i * 8);
        }
    }

    const int nkt = (end - start + 63) / 64;

    // KV stage loader: K 5 chunks + V 5 chunks per thread
    auto load_kv = [&](int st, int t) {
        const int k0 = start + t * 64;
        // K: 2 arrays x 64 rows x 10 chunks = 1280; this thread does ids tid+256i
        #pragma unroll
        for (int i = 0; i < 5; i++) {
            const int id  = tid + i * 256;
            const int isL = id >= 640;
            const int id2 = isL ? id - 640 : id;
            const int r   = id2 / 10;
            const int c8  = (id2 % 10) * 8;
            const int kr  = min(k0 + r, S - 1);
            const size_t so = ((size_t)h * S + kr) * HDIM + c8;
            const uint32_t dst = (isL ? uKl : uKh) +
                (uint32_t)(st * ATT_K + r * QSTR + c8) * 2u;
            cp16(dst, (isL ? gKl : gKh) + so);
        }
        // V: 2 arrays x 80 rows x 8 chunks = 1280
        #pragma unroll
        for (int i = 0; i < 5; i++) {
            const int id  = tid + i * 256;
            const int isL = id >= 640;
            const int id2 = isL ? id - 640 : id;
            const int r   = id2 >> 3;
            const int c8  = (id2 & 7) * 8;
            const size_t so = ((size_t)(h * HDIM + r)) * S + k0 + c8;
            const uint32_t dst = (isL ? uVl : uVh) +
                (uint32_t)(st * ATT_V + r * VSTR + c8) * 2u;
            cp16(dst, (isL ? gVl : gVh) + so);
        }
    };

    load_kv(0, 0);
    CP_COMMIT();

    float acc_o[10][4];
    #pragma unroll
    for (int n = 0; n < 10; n++)
        #pragma unroll
        for (int r = 0; r < 4; r++) acc_o[n][r] = 0.f;
    float m0 = -INFINITY, m1 = -INFINITY, l0 = 0.f, l1 = 0.f;

    for (int t = 0; t < nkt; t++) {
        const int b = t & 1;
        if (t + 1 < nkt) { load_kv(1 - b, t + 1); CP_COMMIT(); CP_WAIT(1); }
        else             { CP_WAIT(0); }
        __syncthreads();

        const uint32_t kB = (uint32_t)(b * ATT_K) * 2u;
        const uint32_t vB = (uint32_t)(b * ATT_V) * 2u;

        // ---- QK^T: 5 k16-blocks, 3-MMA hi/lo split ----
        float acc_s[8][4];
        #pragma unroll
        for (int n = 0; n < 8; n++)
            #pragma unroll
            for (int r = 0; r < 4; r++) acc_s[n][r] = 0.f;

        const int mrow = lane & 7;
        const int msel = lane >> 3;          // 0..3
        #pragma unroll
        for (int kk = 0; kk < 5; kk++) {
            const int kb = kk * 16;
            uint32_t ah[4], al[4];
            {
                const int qrow = wq + (lane & 15);
                const int qcol = kb + ((lane & 16) ? 8 : 0);
                const uint32_t off = (uint32_t)(qrow * QSTR + qcol) * 2u;
                ldsm4(ah, uQh + off);
                ldsm4(al, uQl + off);
            }
            #pragma unroll
            for (int np = 0; np < 4; np++) {
                const int krow = np * 16 + (msel >> 1) * 8 + mrow;
                const int kcol = kb + (msel & 1) * 8;
                const uint32_t off = (uint32_t)(krow * QSTR + kcol) * 2u;
                uint32_t bh4[4], bl4[4];
                ldsm4(bh4, uKh + kB + off);
                ldsm4(bl4, uKl + kB + off);
                mma_f16(acc_s[2 * np],     ah, bh4 + 0);
                mma_f16(acc_s[2 * np],     al, bh4 + 0);
                mma_f16(acc_s[2 * np],     ah, bl4 + 0);
                mma_f16(acc_s[2 * np + 1], ah, bh4 + 2);
                mma_f16(acc_s[2 * np + 1], al, bh4 + 2);
                mma_f16(acc_s[2 * np + 1], ah, bl4 + 2);
            }
        }

        // ---- mask + online softmax ----
        const int k0 = start + t * 64;
        const int nv = end - k0;
        float mt0 = -INFINITY, mt1 = -INFINITY;
        #pragma unroll
        for (int nt = 0; nt < 8; nt++) {
            #pragma unroll
            for (int j = 0; j < 2; j++) {
                const int c = nt * 8 + 2 * t4 + j;
                if (c >= nv) { acc_s[nt][j] = -1e30f; acc_s[nt][2 + j] = -1e30f; }
                mt0 = fmaxf(mt0, acc_s[nt][j]);
                mt1 = fmaxf(mt1, acc_s[nt][2 + j]);
            }
        }
        mt0 = fmaxf(mt0, __shfl_xor_sync(0xffffffffu, mt0, 1));
        mt0 = fmaxf(mt0, __shfl_xor_sync(0xffffffffu, mt0, 2));
        mt1 = fmaxf(mt1, __shfl_xor_sync(0xffffffffu, mt1, 1));
        mt1 = fmaxf(mt1, __shfl_xor_sync(0xffffffffu, mt1, 2));

        const float mn0 = fmaxf(m0, mt0), mn1 = fmaxf(m1, mt1);
        const float al0 = __expf(m0 - mn0), al1 = __expf(m1 - mn1);
        m0 = mn0; m1 = mn1;

        float rs0 = 0.f, rs1 = 0.f;
        #pragma unroll
        for (int nt = 0; nt < 8; nt++) {
            #pragma unroll
            for (int j = 0; j < 2; j++) {
                const float p0 = __expf(acc_s[nt][j]     - m0);
                const float p1 = __expf(acc_s[nt][2 + j] - m1);
                acc_s[nt][j]     = p0;
                acc_s[nt][2 + j] = p1;
                rs0 += p0; rs1 += p1;
            }
        }
        rs0 += __shfl_xor_sync(0xffffffffu, rs0, 1);
        rs0 += __shfl_xor_sync(0xffffffffu, rs0, 2);
        rs1 += __shfl_xor_sync(0xffffffffu, rs1, 1);
        rs1 += __shfl_xor_sync(0xffffffffu, rs1, 2);
        l0 = l0 * al0 + rs0;
        l1 = l1 * al1 + rs1;

        #pragma unroll
        for (int n = 0; n < 10; n++) {
            acc_o[n][0] *= al0; acc_o[n][1] *= al0;
            acc_o[n][2] *= al1; acc_o[n][3] *= al1;
        }

        // ---- pack P into fp16 A-fragments (registers only) ----
        uint32_t pk[4][4];
        #pragma unroll
        for (int kk = 0; kk < 4; kk++) {
            pk[kk][0] = pack_h2(acc_s[2 * kk][0],     acc_s[2 * kk][1]);
            pk[kk][1] = pack_h2(acc_s[2 * kk][2],     acc_s[2 * kk][3]);
            pk[kk][2] = pack_h2(acc_s[2 * kk + 1][0], acc_s[2 * kk + 1][1]);
            pk[kk][3] = pack_h2(acc_s[2 * kk + 1][2], acc_s[2 * kk + 1][3]);
        }

        // ---- PV: 4 k16-blocks, V-side hi/lo split ----
        #pragma unroll
        for (int kk = 0; kk < 4; kk++) {
            const int kb = kk * 16;
            #pragma unroll
            for (int vp = 0; vp < 5; vp++) {
                const int vrow = vp * 16 + (msel >> 1) * 8 + mrow;
                const int vcol = kb + (msel & 1) * 8;
                const uint32_t off = (uint32_t)(vrow * VSTR + vcol) * 2u;
                uint32_t vh4[4], vl4[4];
                ldsm4(vh4, uVh + vB + off);
                ldsm4(vl4, uVl + vB + off);
                mma_f16(acc_o[2 * vp],     pk[kk], vh4 + 0);
                mma_f16(acc_o[2 * vp],     pk[kk], vl4 + 0);
                mma_f16(acc_o[2 * vp + 1], pk[kk], vh4 + 2);
                mma_f16(acc_o[2 * vp + 1], pk[kk], vl4 + 2);
            }
        }
        __syncthreads();
    }

    // ---- epilogue ----
    const float inv0 = 1.f / l0, inv1 = 1.f / l1;
    const int r0 = q0 + wq + gid, r1 = r0 + 8;
    #pragma unroll
    for (int nt = 0; nt < 10; nt++) {
        const int col = h * HDIM + nt * 8 + 2 * t4;
        if (r0 < end) {
            float2 v = make_float2(acc_o[nt][0] * inv0, acc_o[nt][1] * inv0);
            *reinterpret_cast<float2*>(&out[(size_t)r0 * D_MODEL + col]) = v;
        }
        if (r1 < end) {
            float2 v = make_float2(acc_o[nt][2] * inv1, acc_o[nt][3] * inv1);
            *reinterpret_cast<float2*>(&out[(size_t)r1 * D_MODEL + col]) = v;
        }
    }
}

// ======================= launch ============================================
extern "C" void kernel_launch(void* const* d_in, const int* in_sizes, int n_in,
                              void* d_out, int out_size)
{
    const float* hidden = (const float*)d_in[0];
    const int*   cu     = (const int*)  d_in[1];
    const float* rope   = (const float*)d_in[2];
    const float* w_qkv  = (const float*)d_in[3];
    const float* b_qkv  = (const float*)d_in[4];
    const float* w_proj = (const float*)d_in[5];
    const float* b_proj = (const float*)d_in[6];
    float* out = (float*)d_out;

    const int S     = in_sizes[0] / D_MODEL;
    const int n_seg = in_sizes[1] - 1;

    float *qkv_p, *attn_p, *wqkv_t, *wproj_t;
    __half *qh, *ql, *kh, *kl, *vh, *vl;
    cudaGetSymbolAddress((void**)&qkv_p,   g_qkv);
    cudaGetSymbolAddress((void**)&attn_p,  g_attn);
    cudaGetSymbolAddress((void**)&wqkv_t,  g_wqkv_t);
    cudaGetSymbolAddress((void**)&wproj_t, g_wproj_t);
    cudaGetSymbolAddress((void**)&qh, g_qh);
    cudaGetSymbolAddress((void**)&ql, g_ql);
    cudaGetSymbolAddress((void**)&kh, g_kh);
    cudaGetSymbolAddress((void**)&kl, g_kl);
    cudaGetSymbolAddress((void**)&vh, g_vh);
    cudaGetSymbolAddress((void**)&vl, g_vl);

    cudaFuncSetAttribute(gemm_tf32, cudaFuncAttributeMaxDynamicSharedMemorySize, GEMM_SMEM);
    cudaFuncSetAttribute(attn_tc,   cudaFuncAttributeMaxDynamicSharedMemorySize, ATC_SMEM);

    // 0) transpose weights to K-major
    {
        dim3 blk(32, 8);
        transpose_kernel<<<dim3(3 * D_MODEL / 32, D_MODEL / 32), blk>>>(w_qkv, wqkv_t, D_MODEL, 3 * D_MODEL);
        transpose_kernel<<<dim3(D_MODEL / 32, D_MODEL / 32), blk>>>(w_proj, wproj_t, D_MODEL, D_MODEL);
    }

    // 1) QKV projection (tf32 mma.sync)
    gemm_tf32<<<dim3(3 * D_MODEL / 128, S / 128), 256, GEMM_SMEM>>>(
        hidden, wqkv_t, b_qkv, qkv_p, S, 3 * D_MODEL, D_MODEL);

    // 2) RoPE + hi/lo split scatter; V transpose + split
    rope_scatter<<<S, 256>>>(qkv_p, rope, qh, ql, kh, kl, S);
    vtrans<<<dim3(S / 64, NHEADS), 256>>>(qkv_p, vh, vl, S);

    // 3) block-diagonal attention (fp16-split tensor cores)
    attn_tc<<<dim3(S / 128, NHEADS), 256, ATC_SMEM>>>(
        qh, ql, kh, kl, vh, vl, cu, n_seg, attn_p, S);

    // 4) output projection (tf32 mma.sync)
    gemm_tf32<<<dim3(D_MODEL / 128, S / 128), 256, GEMM_SMEM>>>(
        attn_p, wproj_t, b_proj, out, S, D_MODEL, D_MODEL);
}

// round 7
// speedup vs baseline: 1.8477x; 1.2202x over previous
#include <cuda_runtime.h>
#include <cuda_fp16.h>
#include <math.h>
#include <cstdint>

#define D_MODEL 1280
#define NHEADS  16
#define HDIM    80
#define S_MAX   4096

// ---------------- scratch (device globals; no allocation allowed) ----------
__device__ float  g_qkv[S_MAX * 3 * D_MODEL];
__device__ __half g_hh[S_MAX * D_MODEL];                 // hidden fp16
__device__ __half g_attnh[S_MAX * D_MODEL];              // attn out fp16
__device__ __half g_wqkv_h[3 * D_MODEL * D_MODEL];       // (3D, D) K-major hi
__device__ __half g_wqkv_l[3 * D_MODEL * D_MODEL];       // lo
__device__ __half g_wproj_h[D_MODEL * D_MODEL];
__device__ __half g_wproj_l[D_MODEL * D_MODEL];
// fp16 hi/lo split attention tensors
__device__ __half g_qh[NHEADS * S_MAX * HDIM];           // (H,S,80) scaled
__device__ __half g_ql[NHEADS * S_MAX * HDIM];
__device__ __half g_kh[NHEADS * S_MAX * HDIM];
__device__ __half g_kl[NHEADS * S_MAX * HDIM];
__device__ __half g_vh[NHEADS * HDIM * S_MAX];           // (H,80,S) transposed
__device__ __half g_vl[NHEADS * HDIM * S_MAX];

// ======================= helpers ===========================================
__device__ __forceinline__ uint32_t smem_u32(const void* p) {
    uint32_t a;
    asm("{ .reg .u64 t; cvta.to.shared.u64 t, %1; cvt.u32.u64 %0, t; }" : "=r"(a) : "l"(p));
    return a;
}
__device__ __forceinline__ void cp16(uint32_t dst, const void* src) {
    asm volatile("cp.async.cg.shared.global [%0], [%1], 16;" :: "r"(dst), "l"(src));
}
#define CP_COMMIT() asm volatile("cp.async.commit_group;" ::: "memory")
#define CP_WAIT(n)  asm volatile("cp.async.wait_group %0;" :: "n"(n) : "memory")

__device__ __forceinline__ void mma_f16(float* c, const uint32_t* a, const uint32_t* b) {
    asm volatile(
        "mma.sync.aligned.m16n8k16.row.col.f32.f16.f16.f32 "
        "{%0,%1,%2,%3}, {%4,%5,%6,%7}, {%8,%9}, {%0,%1,%2,%3};"
        : "+f"(c[0]), "+f"(c[1]), "+f"(c[2]), "+f"(c[3])
        : "r"(a[0]), "r"(a[1]), "r"(a[2]), "r"(a[3]), "r"(b[0]), "r"(b[1]));
}
__device__ __forceinline__ void ldsm4(uint32_t* r, uint32_t addr) {
    asm volatile("ldmatrix.sync.aligned.m8n8.x4.shared.b16 {%0,%1,%2,%3}, [%4];"
        : "=r"(r[0]), "=r"(r[1]), "=r"(r[2]), "=r"(r[3]) : "r"(addr));
}
__device__ __forceinline__ uint32_t pack_h2(float lo, float hi) {
    __half2 h = __floats2half2_rn(lo, hi);
    return *reinterpret_cast<uint32_t*>(&h);
}

// ======================= weight transpose + fp16 split =====================
// in (K, N) fp32 -> hi/lo (N, K) fp16
__global__ void wsplit(const float* __restrict__ in, __half* __restrict__ oh,
                       __half* __restrict__ ol, int K, int N) {
    __shared__ float tile[32][33];
    const int k0 = blockIdx.y * 32, n0 = blockIdx.x * 32;
    const int tx = threadIdx.x, ty = threadIdx.y;
    #pragma unroll
    for (int i = ty; i < 32; i += 8)
        tile[i][tx] = in[(size_t)(k0 + i) * N + n0 + tx];
    __syncthreads();
    #pragma unroll
    for (int i = ty; i < 32; i += 8) {
        const float v = tile[tx][i];
        const __half hi = __float2half_rn(v);
        const size_t o = (size_t)(n0 + i) * K + k0 + tx;
        oh[o] = hi;
        ol[o] = __float2half_rn(v - __half2float(hi));
    }
}

// ======================= fp32 -> fp16 convert ==============================
__global__ void f2h(const float* __restrict__ in, __half* __restrict__ out) {
    const int i = (blockIdx.x * blockDim.x + threadIdx.x) * 4;
    float4 v = *reinterpret_cast<const float4*>(in + i);
    __half2 a = __floats2half2_rn(v.x, v.y);
    __half2 b = __floats2half2_rn(v.z, v.w);
    uint2 pk;
    pk.x = *reinterpret_cast<uint32_t*>(&a);
    pk.y = *reinterpret_cast<uint32_t*>(&b);
    *reinterpret_cast<uint2*>(out + i) = pk;
}

// ======================= fp16 weight-split GEMM ============================
// C(MxN) = A(MxK fp16) @ (Bh+Bl)(NxK fp16)^T + bias.  128x128, BK=32, 2-stage.
#define ASTR 40
#define GEMM_STAGE (3 * 128 * ASTR)          // halves per stage
#define GEMM_SMEM  69632                     // >= max(2*stage*2B, 128*132*4B)

__global__ __launch_bounds__(256)
void gemm_f16(const __half* __restrict__ A, const __half* __restrict__ Bh,
              const __half* __restrict__ Bl, const float* __restrict__ bias,
              float* __restrict__ C, int M, int N, int K)
{
    extern __shared__ __half smh[];
    const int tid  = threadIdx.x;
    const int warp = tid >> 5, lane = tid & 31;
    const int gid  = lane >> 2, t4 = lane & 3;
    const int mrow = lane & 7, msel = lane >> 3;
    const int wm0  = (warp & 3) * 32;
    const int wn0  = (warp >> 2) * 64;
    const int bx = blockIdx.x, by = blockIdx.y;

    const __half* Ab  = A  + (size_t)by * 128 * K;
    const __half* Bhb = Bh + (size_t)bx * 128 * K;
    const __half* Blb = Bl + (size_t)bx * 128 * K;
    const int NS = K / 32;
    const uint32_t sb = smem_u32(smh);

    auto load_stage = [&](int s, int ks) {
        #pragma unroll
        for (int i = 0; i < 6; i++) {
            const int id    = tid + i * 256;       // 0..1535
            const int which = id >> 9;             // 0:A 1:Bh 2:Bl
            const int id2   = id & 511;
            const int row   = id2 >> 2;
            const int c8    = (id2 & 3) * 8;
            const __half* src = (which == 0 ? Ab : (which == 1 ? Bhb : Blb))
                                + (size_t)row * K + ks * 32 + c8;
            const uint32_t dst = sb +
                (uint32_t)(s * GEMM_STAGE + which * 128 * ASTR + row * ASTR + c8) * 2u;
            cp16(dst, src);
        }
        CP_COMMIT();
    };

    float acc[2][8][4];
    #pragma unroll
    for (int mt = 0; mt < 2; mt++)
        #pragma unroll
        for (int nt = 0; nt < 8; nt++)
            #pragma unroll
            for (int r = 0; r < 4; r++) acc[mt][nt][r] = 0.f;

    load_stage(0, 0);
    for (int ks = 0; ks < NS; ks++) {
        const int s = ks & 1;
        if (ks + 1 < NS) { load_stage(1 - s, ks + 1); CP_WAIT(1); }
        else             { CP_WAIT(0); }
        __syncthreads();

        const uint32_t uA  = sb + (uint32_t)(s * GEMM_STAGE) * 2u;
        const uint32_t uBh = uA + (uint32_t)(128 * ASTR) * 2u;
        const uint32_t uBl = uBh + (uint32_t)(128 * ASTR) * 2u;

        #pragma unroll
        for (int kk = 0; kk < 2; kk++) {
            const int kb = kk * 16;
            uint32_t a0[4], a1[4];
            const uint32_t aoff = (uint32_t)((wm0 + (lane & 15)) * ASTR + kb
                                             + ((lane & 16) ? 8 : 0)) * 2u;
            ldsm4(a0, uA + aoff);
            ldsm4(a1, uA + aoff + (uint32_t)(16 * ASTR) * 2u);
            #pragma unroll
            for (int np = 0; np < 4; np++) {
                const uint32_t boff = (uint32_t)((wn0 + np * 16 + (msel >> 1) * 8 + mrow) * ASTR
                                                 + kb + (msel & 1) * 8) * 2u;
                uint32_t bh4[4], bl4[4];
                ldsm4(bh4, uBh + boff);
                ldsm4(bl4, uBl + boff);
                mma_f16(acc[0][2 * np],     a0, bh4 + 0);
                mma_f16(acc[0][2 * np],     a0, bl4 + 0);
                mma_f16(acc[0][2 * np + 1], a0, bh4 + 2);
                mma_f16(acc[0][2 * np + 1], a0, bl4 + 2);
                mma_f16(acc[1][2 * np],     a1, bh4 + 0);
                mma_f16(acc[1][2 * np],     a1, bl4 + 0);
                mma_f16(acc[1][2 * np + 1], a1, bh4 + 2);
                mma_f16(acc[1][2 * np + 1], a1, bl4 + 2);
            }
        }
        __syncthreads();
    }

    // epilogue via fp32 smem staging
    float* Cs = reinterpret_cast<float*>(smh);
    #pragma unroll
    for (int mt = 0; mt < 2; mt++)
        #pragma unroll
        for (int nt = 0; nt < 8; nt++) {
            const int row = wm0 + mt * 16 + gid;
            const int col = wn0 + nt * 8 + t4 * 2;
            Cs[row * 132 + col]           = acc[mt][nt][0];
            Cs[row * 132 + col + 1]       = acc[mt][nt][1];
            Cs[(row + 8) * 132 + col]     = acc[mt][nt][2];
            Cs[(row + 8) * 132 + col + 1] = acc[mt][nt][3];
        }
    __syncthreads();
    #pragma unroll
    for (int it = 0; it < 16; it++) {
        const int id  = tid + it * 256;
        const int row = id >> 5;
        const int c4  = (id & 31) * 4;
        float4 v = *reinterpret_cast<const float4*>(&Cs[row * 132 + c4]);
        const int gc = bx * 128 + c4;
        v.x += bias[gc + 0]; v.y += bias[gc + 1]; v.z += bias[gc + 2]; v.w += bias[gc + 3];
        *reinterpret_cast<float4*>(&C[(size_t)(by * 128 + row) * N + gc]) = v;
    }
}

// ======================= RoPE + split-scatter ==============================
__global__ void rope_scatter(const float* __restrict__ qkv,
                             const float* __restrict__ freqs,
                             __half* __restrict__ Qh, __half* __restrict__ Ql,
                             __half* __restrict__ Kh, __half* __restrict__ Kl,
                             int S)
{
    const int s = blockIdx.x;
    const float* base = qkv + (size_t)s * (3 * D_MODEL);
    const float scale = 0.11180339887498949f;   // 1/sqrt(80)
    for (int idx = threadIdx.x; idx < NHEADS * HDIM; idx += blockDim.x) {
        const int h = idx / HDIM;
        const int d = idx % HDIM;
        const int dd = (d < 40) ? d : d - 40;
        const float f  = freqs[(size_t)s * 40 + dd];
        const float cs = cosf(f), sn = sinf(f);
        const float q1 = base[h * HDIM + dd];
        const float q2 = base[h * HDIM + dd + 40];
        const float k1 = base[D_MODEL + h * HDIM + dd];
        const float k2 = base[D_MODEL + h * HDIM + dd + 40];
        float qo = (d < 40) ? (q1 * cs - q2 * sn) : (q1 * sn + q2 * cs);
        const float ko = (d < 40) ? (k1 * cs - k2 * sn) : (k1 * sn + k2 * cs);
        qo *= scale;
        const size_t o = ((size_t)h * S + s) * HDIM + d;
        const __half qhi = __float2half_rn(qo);
        Qh[o] = qhi;
        Ql[o] = __float2half_rn(qo - __half2float(qhi));
        const __half khi = __float2half_rn(ko);
        Kh[o] = khi;
        Kl[o] = __float2half_rn(ko - __half2float(khi));
    }
}

// ======================= V transpose + split ===============================
__global__ void vtrans(const float* __restrict__ qkv,
                       __half* __restrict__ Vh, __half* __restrict__ Vl, int S)
{
    __shared__ float tile[64][84];
    const int tid = threadIdx.x;
    const int h  = blockIdx.y;
    const int s0 = blockIdx.x * 64;
    {
        const int sl = tid >> 2;
        const int dc = (tid & 3) * 20;
        const float* src = qkv + (size_t)(s0 + sl) * (3 * D_MODEL) + 2 * D_MODEL + h * HDIM + dc;
        #pragma unroll
        for (int i = 0; i < 5; i++) {
            float4 v = *reinterpret_cast<const float4*>(src + i * 4);
            tile[sl][dc + i * 4 + 0] = v.x;
            tile[sl][dc + i * 4 + 1] = v.y;
            tile[sl][dc + i * 4 + 2] = v.z;
            tile[sl][dc + i * 4 + 3] = v.w;
        }
    }
    __syncthreads();
    if (tid < 160) {
        const int d  = tid >> 1;
        const int sh = (tid & 1) * 32;
        const size_t o = ((size_t)(h * HDIM + d)) * S + s0 + sh;
        #pragma unroll
        for (int j = 0; j < 16; j++) {
            const float v0 = tile[sh + 2 * j][d];
            const float v1 = tile[sh + 2 * j + 1][d];
            const __half h0 = __float2half_rn(v0);
            const __half h1 = __float2half_rn(v1);
            __half2 hi; hi.x = h0; hi.y = h1;
            __half2 lo;
            lo.x = __float2half_rn(v0 - __half2float(h0));
            lo.y = __float2half_rn(v1 - __half2float(h1));
            *reinterpret_cast<__half2*>(&Vh[o + 2 * j]) = hi;
            *reinterpret_cast<__half2*>(&Vl[o + 2 * j]) = lo;
        }
    }
}

// ======================= fp16-split tensor-core attention ==================
// CTA = (q-tile 256, head), 16 warps x 16 q-rows, KV tile 64, 2-stage cp.async.
#define QSTR 88
#define VSTR 72
#define ATT_Q  (256 * QSTR)
#define ATT_K  (64 * QSTR)
#define ATT_V  (80 * VSTR)
#define ATC_SMEM ((2 * ATT_Q + 4 * ATT_K + 4 * ATT_V) * 2)   // 181248 B

__global__ __launch_bounds__(512)
void attn_tc(const __half* __restrict__ gQh, const __half* __restrict__ gQl,
             const __half* __restrict__ gKh, const __half* __restrict__ gKl,
             const __half* __restrict__ gVh, const __half* __restrict__ gVl,
             const int* __restrict__ cu, int n_seg,
             __half* __restrict__ outh, int S)
{
    extern __shared__ __half sh[];
    __half* Qh = sh;
    __half* Ql = Qh + ATT_Q;
    __half* Kh = Ql + ATT_Q;           // [2][ATT_K]
    __half* Kl = Kh + 2 * ATT_K;
    __half* Vh = Kl + 2 * ATT_K;       // [2][ATT_V]
    __half* Vl = Vh + 2 * ATT_V;

    const uint32_t uQh = smem_u32(Qh), uQl = smem_u32(Ql);
    const uint32_t uKh = smem_u32(Kh), uKl = smem_u32(Kl);
    const uint32_t uVh = smem_u32(Vh), uVl = smem_u32(Vl);

    const int tid  = threadIdx.x;
    const int warp = tid >> 5, lane = tid & 31;
    const int gid  = lane >> 2, t4 = lane & 3;
    const int mrow = lane & 7, msel = lane >> 3;
    const int wq   = warp * 16;
    const int h    = blockIdx.y;
    const int q0   = blockIdx.x * 256;

    int start = 0, end = S;
    for (int i = 0; i < n_seg; i++) {
        int a = cu[i], b = cu[i + 1];
        if (a <= q0 && q0 < b) { start = a; end = b; }
    }

    // ---- Q load (cp.async): 10 chunks/thread ----
    #pragma unroll
    for (int i = 0; i < 10; i++) {
        const int id  = tid + i * 512;        // 0..5119
        const int isL = id >= 2560;
        const int id2 = isL ? id - 2560 : id;
        const int r   = id2 / 10;
        const int c8  = (id2 % 10) * 8;
        const size_t so = ((size_t)h * S + q0 + r) * HDIM + c8;
        const uint32_t dst = (isL ? uQl : uQh) + (uint32_t)(r * QSTR + c8) * 2u;
        cp16(dst, (isL ? gQl : gQh) + so);
    }

    const int nkt = (end - start + 63) / 64;

    auto load_kv = [&](int st, int t) {
        const int k0 = start + t * 64;
        #pragma unroll
        for (int i = 0; i < 5; i++) {
            const int id = tid + i * 512;     // 0..2559
            if (id < 1280) {                  // K
                const int isL = id >= 640;
                const int id2 = isL ? id - 640 : id;
                const int r   = id2 / 10;
                const int c8  = (id2 % 10) * 8;
                const size_t so = ((size_t)h * S + k0 + r) * HDIM + c8;
                const uint32_t dst = (isL ? uKl : uKh) +
                    (uint32_t)(st * ATT_K + r * QSTR + c8) * 2u;
                cp16(dst, (isL ? gKl : gKh) + so);
            } else {                          // V
                const int idv = id - 1280;
                const int isL = idv >= 640;
                const int id2 = isL ? idv - 640 : idv;
                const int r   = id2 >> 3;
                const int c8  = (id2 & 7) * 8;
                const size_t so = ((size_t)(h * HDIM + r)) * S + k0 + c8;
                const uint32_t dst = (isL ? uVl : uVh) +
                    (uint32_t)(st * ATT_V + r * VSTR + c8) * 2u;
                cp16(dst, (isL ? gVl : gVh) + so);
            }
        }
    };

    load_kv(0, 0);
    CP_COMMIT();

    float acc_o[10][4];
    #pragma unroll
    for (int n = 0; n < 10; n++)
        #pragma unroll
        for (int r = 0; r < 4; r++) acc_o[n][r] = 0.f;
    float m0 = -INFINITY, m1 = -INFINITY, l0 = 0.f, l1 = 0.f;

    for (int t = 0; t < nkt; t++) {
        const int b = t & 1;
        if (t + 1 < nkt) { load_kv(1 - b, t + 1); CP_COMMIT(); CP_WAIT(1); }
        else             { CP_WAIT(0); }
        __syncthreads();

        const uint32_t kB = (uint32_t)(b * ATT_K) * 2u;
        const uint32_t vB = (uint32_t)(b * ATT_V) * 2u;

        // ---- QK^T: 5 k16-blocks, 3-MMA hi/lo split ----
        float acc_s[8][4];
        #pragma unroll
        for (int n = 0; n < 8; n++)
            #pragma unroll
            for (int r = 0; r < 4; r++) acc_s[n][r] = 0.f;

        #pragma unroll
        for (int kk = 0; kk < 5; kk++) {
            const int kb = kk * 16;
            uint32_t ah[4], al[4];
            {
                const uint32_t off = (uint32_t)((wq + (lane & 15)) * QSTR + kb
                                                + ((lane & 16) ? 8 : 0)) * 2u;
                ldsm4(ah, uQh + off);
                ldsm4(al, uQl + off);
            }
            #pragma unroll
            for (int np = 0; np < 4; np++) {
                const uint32_t off = (uint32_t)((np * 16 + (msel >> 1) * 8 + mrow) * QSTR
                                                + kb + (msel & 1) * 8) * 2u;
                uint32_t bh4[4], bl4[4];
                ldsm4(bh4, uKh + kB + off);
                ldsm4(bl4, uKl + kB + off);
                mma_f16(acc_s[2 * np],     ah, bh4 + 0);
                mma_f16(acc_s[2 * np],     al, bh4 + 0);
                mma_f16(acc_s[2 * np],     ah, bl4 + 0);
                mma_f16(acc_s[2 * np + 1], ah, bh4 + 2);
                mma_f16(acc_s[2 * np + 1], al, bh4 + 2);
                mma_f16(acc_s[2 * np + 1], ah, bl4 + 2);
            }
        }

        // ---- mask + online softmax ----
        const int k0 = start + t * 64;
        const int nv = end - k0;
        float mt0 = -INFINITY, mt1 = -INFINITY;
        #pragma unroll
        for (int nt = 0; nt < 8; nt++) {
            #pragma unroll
            for (int j = 0; j < 2; j++) {
                const int c = nt * 8 + 2 * t4 + j;
                if (c >= nv) { acc_s[nt][j] = -1e30f; acc_s[nt][2 + j] = -1e30f; }
                mt0 = fmaxf(mt0, acc_s[nt][j]);
                mt1 = fmaxf(mt1, acc_s[nt][2 + j]);
            }
        }
        mt0 = fmaxf(mt0, __shfl_xor_sync(0xffffffffu, mt0, 1));
        mt0 = fmaxf(mt0, __shfl_xor_sync(0xffffffffu, mt0, 2));
        mt1 = fmaxf(mt1, __shfl_xor_sync(0xffffffffu, mt1, 1));
        mt1 = fmaxf(mt1, __shfl_xor_sync(0xffffffffu, mt1, 2));

        const float mn0 = fmaxf(m0, mt0), mn1 = fmaxf(m1, mt1);
        const float al0 = __expf(m0 - mn0), al1 = __expf(m1 - mn1);
        m0 = mn0; m1 = mn1;

        float rs0 = 0.f, rs1 = 0.f;
        #pragma unroll
        for (int nt = 0; nt < 8; nt++) {
            #pragma unroll
            for (int j = 0; j < 2; j++) {
                const float p0 = __expf(acc_s[nt][j]     - m0);
                const float p1 = __expf(acc_s[nt][2 + j] - m1);
                acc_s[nt][j]     = p0;
                acc_s[nt][2 + j] = p1;
                rs0 += p0; rs1 += p1;
            }
        }
        rs0 += __shfl_xor_sync(0xffffffffu, rs0, 1);
        rs0 += __shfl_xor_sync(0xffffffffu, rs0, 2);
        rs1 += __shfl_xor_sync(0xffffffffu, rs1, 1);
        rs1 += __shfl_xor_sync(0xffffffffu, rs1, 2);
        l0 = l0 * al0 + rs0;
        l1 = l1 * al1 + rs1;

        #pragma unroll
        for (int n = 0; n < 10; n++) {
            acc_o[n][0] *= al0; acc_o[n][1] *= al0;
            acc_o[n][2] *= al1; acc_o[n][3] *= al1;
        }

        // ---- pack P into fp16 A-fragments ----
        uint32_t pk[4][4];
        #pragma unroll
        for (int kk = 0; kk < 4; kk++) {
            pk[kk][0] = pack_h2(acc_s[2 * kk][0],     acc_s[2 * kk][1]);
            pk[kk][1] = pack_h2(acc_s[2 * kk][2],     acc_s[2 * kk][3]);
            pk[kk][2] = pack_h2(acc_s[2 * kk + 1][0], acc_s[2 * kk + 1][1]);
            pk[kk][3] = pack_h2(acc_s[2 * kk + 1][2], acc_s[2 * kk + 1][3]);
        }

        // ---- PV: 4 k16-blocks, V-side hi/lo split ----
        #pragma unroll
        for (int kk = 0; kk < 4; kk++) {
            const int kb = kk * 16;
            #pragma unroll
            for (int vp = 0; vp < 5; vp++) {
                const uint32_t off = (uint32_t)((vp * 16 + (msel >> 1) * 8 + mrow) * VSTR
                                                + kb + (msel & 1) * 8) * 2u;
                uint32_t vh4[4], vl4[4];
                ldsm4(vh4, uVh + vB + off);
                ldsm4(vl4, uVl + vB + off);
                mma_f16(acc_o[2 * vp],     pk[kk], vh4 + 0);
                mma_f16(acc_o[2 * vp],     pk[kk], vl4 + 0);
                mma_f16(acc_o[2 * vp + 1], pk[kk], vh4 + 2);
                mma_f16(acc_o[2 * vp + 1], pk[kk], vl4 + 2);
            }
        }
        __syncthreads();
    }

    // ---- epilogue: write fp16 (rounding budgeted by proj GEMM) ----
    const float inv0 = 1.f / l0, inv1 = 1.f / l1;
    const int r0 = q0 + wq + gid, r1 = r0 + 8;
    #pragma unroll
    for (int nt = 0; nt < 10; nt++) {
        const int col = h * HDIM + nt * 8 + 2 * t4;
        __half2 v0 = __floats2half2_rn(acc_o[nt][0] * inv0, acc_o[nt][1] * inv0);
        __half2 v1 = __floats2half2_rn(acc_o[nt][2] * inv1, acc_o[nt][3] * inv1);
        *reinterpret_cast<__half2*>(&outh[(size_t)r0 * D_MODEL + col]) = v0;
        *reinterpret_cast<__half2*>(&outh[(size_t)r1 * D_MODEL + col]) = v1;
    }
}

// ======================= launch ============================================
extern "C" void kernel_launch(void* const* d_in, const int* in_sizes, int n_in,
                              void* d_out, int out_size)
{
    const float* hidden = (const float*)d_in[0];
    const int*   cu     = (const int*)  d_in[1];
    const float* rope   = (const float*)d_in[2];
    const float* w_qkv  = (const float*)d_in[3];
    const float* b_qkv  = (const float*)d_in[4];
    const float* w_proj = (const float*)d_in[5];
    const float* b_proj = (const float*)d_in[6];
    float* out = (float*)d_out;

    const int S     = in_sizes[0] / D_MODEL;
    const int n_seg = in_sizes[1] - 1;

    float *qkv_p;
    __half *hh, *attnh, *wqh, *wql, *wph, *wpl, *qh, *ql, *kh, *kl, *vh, *vl;
    cudaGetSymbolAddress((void**)&qkv_p, g_qkv);
    cudaGetSymbolAddress((void**)&hh,    g_hh);
    cudaGetSymbolAddress((void**)&attnh, g_attnh);
    cudaGetSymbolAddress((void**)&wqh,   g_wqkv_h);
    cudaGetSymbolAddress((void**)&wql,   g_wqkv_l);
    cudaGetSymbolAddress((void**)&wph,   g_wproj_h);
    cudaGetSymbolAddress((void**)&wpl,   g_wproj_l);
    cudaGetSymbolAddress((void**)&qh, g_qh);
    cudaGetSymbolAddress((void**)&ql, g_ql);
    cudaGetSymbolAddress((void**)&kh, g_kh);
    cudaGetSymbolAddress((void**)&kl, g_kl);
    cudaGetSymbolAddress((void**)&vh, g_vh);
    cudaGetSymbolAddress((void**)&vl, g_vl);

    cudaFuncSetAttribute(gemm_f16, cudaFuncAttributeMaxDynamicSharedMemorySize, GEMM_SMEM);
    cudaFuncSetAttribute(attn_tc,  cudaFuncAttributeMaxDynamicSharedMemorySize, ATC_SMEM);

    // 0) weight transpose + split; hidden -> fp16
    {
        dim3 blk(32, 8);
        wsplit<<<dim3(3 * D_MODEL / 32, D_MODEL / 32), blk>>>(w_qkv, wqh, wql, D_MODEL, 3 * D_MODEL);
        wsplit<<<dim3(D_MODEL / 32, D_MODEL / 32), blk>>>(w_proj, wph, wpl, D_MODEL, D_MODEL);
        f2h<<<(S * D_MODEL) / (256 * 4), 256>>>(hidden, hh);
    }

    // 1) QKV projection (fp16 weight-split)
    gemm_f16<<<dim3(3 * D_MODEL / 128, S / 128), 256, GEMM_SMEM>>>(
        hh, wqh, wql, b_qkv, qkv_p, S, 3 * D_MODEL, D_MODEL);

    // 2) RoPE + hi/lo split scatter; V transpose + split
    rope_scatter<<<S, 256>>>(qkv_p, rope, qh, ql, kh, kl, S);
    vtrans<<<dim3(S / 64, NHEADS), 256>>>(qkv_p, vh, vl, S);

    // 3) block-diagonal attention (fp16-split tensor cores), fp16 output
    attn_tc<<<dim3(S / 256, NHEADS), 512, ATC_SMEM>>>(
        qh, ql, kh, kl, vh, vl, cu, n_seg, attnh, S);

    // 4) output projection (fp16 weight-split)
    gemm_f16<<<dim3(D_MODEL / 128, S / 128), 256, GEMM_SMEM>>>(
        attnh, wph, wpl, b_proj, out, S, D_MODEL, D_MODEL);
}

// round 10
// speedup vs baseline: 2.3568x; 1.2755x over previous
#include <cuda_runtime.h>
#include <cuda_fp16.h>
#include <math.h>
#include <cstdint>

#define D_MODEL 1280
#define NHEADS  16
#define HDIM    80
#define S_MAX   4096

// ---------------- scratch (device globals; no allocation allowed) ----------
__device__ float  g_qkv[S_MAX * 3 * D_MODEL];
__device__ __half g_hh[S_MAX * D_MODEL];                 // hidden fp16
__device__ __half g_attnh[S_MAX * D_MODEL];              // attn out fp16
__device__ __half g_wqkv_h[3 * D_MODEL * D_MODEL];       // (3D, D) K-major fp16
__device__ __half g_wproj_h[D_MODEL * D_MODEL];
// fp16 hi/lo split attention tensors
__device__ __half g_qh[NHEADS * S_MAX * HDIM];           // (H,S,80) scaled
__device__ __half g_ql[NHEADS * S_MAX * HDIM];
__device__ __half g_kh[NHEADS * S_MAX * HDIM];
__device__ __half g_kl[NHEADS * S_MAX * HDIM];
__device__ __half g_vh[NHEADS * HDIM * S_MAX];           // (H,80,S) transposed
__device__ __half g_vl[NHEADS * HDIM * S_MAX];

// ======================= helpers ===========================================
__device__ __forceinline__ uint32_t smem_u32(const void* p) {
    uint32_t a;
    asm("{ .reg .u64 t; cvta.to.shared.u64 t, %1; cvt.u32.u64 %0, t; }" : "=r"(a) : "l"(p));
    return a;
}
__device__ __forceinline__ void cp16(uint32_t dst, const void* src) {
    asm volatile("cp.async.cg.shared.global [%0], [%1], 16;" :: "r"(dst), "l"(src));
}
#define CP_COMMIT() asm volatile("cp.async.commit_group;" ::: "memory")
#define CP_WAIT(n)  asm volatile("cp.async.wait_group %0;" :: "n"(n) : "memory")

__device__ __forceinline__ void mma_f16(float* c, const uint32_t* a, const uint32_t* b) {
    asm volatile(
        "mma.sync.aligned.m16n8k16.row.col.f32.f16.f16.f32 "
        "{%0,%1,%2,%3}, {%4,%5,%6,%7}, {%8,%9}, {%0,%1,%2,%3};"
        : "+f"(c[0]), "+f"(c[1]), "+f"(c[2]), "+f"(c[3])
        : "r"(a[0]), "r"(a[1]), "r"(a[2]), "r"(a[3]), "r"(b[0]), "r"(b[1]));
}
__device__ __forceinline__ void ldsm4(uint32_t* r, uint32_t addr) {
    asm volatile("ldmatrix.sync.aligned.m8n8.x4.shared.b16 {%0,%1,%2,%3}, [%4];"
        : "=r"(r[0]), "=r"(r[1]), "=r"(r[2]), "=r"(r[3]) : "r"(addr));
}
__device__ __forceinline__ uint32_t pack_h2(float lo, float hi) {
    __half2 h = __floats2half2_rn(lo, hi);
    return *reinterpret_cast<uint32_t*>(&h);
}

// ======================= weight transpose -> fp16 ==========================
// in (K, N) fp32 -> (N, K) fp16
__global__ void wtrans16(const float* __restrict__ in, __half* __restrict__ oh,
                         int K, int N) {
    __shared__ float tile[32][33];
    const int k0 = blockIdx.y * 32, n0 = blockIdx.x * 32;
    const int tx = threadIdx.x, ty = threadIdx.y;
    #pragma unroll
    for (int i = ty; i < 32; i += 8)
        tile[i][tx] = in[(size_t)(k0 + i) * N + n0 + tx];
    __syncthreads();
    #pragma unroll
    for (int i = ty; i < 32; i += 8)
        oh[(size_t)(n0 + i) * K + k0 + tx] = __float2half_rn(tile[tx][i]);
}

// ======================= fp32 -> fp16 convert ==============================
__global__ void f2h(const float* __restrict__ in, __half* __restrict__ out) {
    const int i = (blockIdx.x * blockDim.x + threadIdx.x) * 4;
    float4 v = *reinterpret_cast<const float4*>(in + i);
    __half2 a = __floats2half2_rn(v.x, v.y);
    __half2 b = __floats2half2_rn(v.z, v.w);
    uint2 pk;
    pk.x = *reinterpret_cast<uint32_t*>(&a);
    pk.y = *reinterpret_cast<uint32_t*>(&b);
    *reinterpret_cast<uint2*>(out + i) = pk;
}

// ======================= plain fp16 GEMM ===================================
// C(MxN) = A(MxK fp16) @ B(NxK fp16)^T + bias.  128x128, BK=32, 2-stage.
#define ASTR 40
#define GEMM_STAGE (2 * 128 * ASTR)          // halves per stage (A + B)
#define GEMM_SMEM  69632                     // epilogue fp32 staging dominates

__global__ __launch_bounds__(256)
void gemm_f16(const __half* __restrict__ A, const __half* __restrict__ B,
              const float* __restrict__ bias, float* __restrict__ C,
              int M, int N, int K)
{
    extern __shared__ __half smh[];
    const int tid  = threadIdx.x;
    const int warp = tid >> 5, lane = tid & 31;
    const int gid  = lane >> 2, t4 = lane & 3;
    const int mrow = lane & 7, msel = lane >> 3;
    const int wm0  = (warp & 3) * 32;
    const int wn0  = (warp >> 2) * 64;
    const int bx = blockIdx.x, by = blockIdx.y;

    const __half* Ab = A + (size_t)by * 128 * K;
    const __half* Bb = B + (size_t)bx * 128 * K;
    const int NS = K / 32;
    const uint32_t sb = smem_u32(smh);

    auto load_stage = [&](int s, int ks) {
        #pragma unroll
        for (int i = 0; i < 4; i++) {
            const int id    = tid + i * 256;       // 0..1023
            const int isB   = id >> 9;
            const int id2   = id & 511;
            const int row   = id2 >> 2;
            const int c8    = (id2 & 3) * 8;
            const __half* src = (isB ? Bb : Ab) + (size_t)row * K + ks * 32 + c8;
            const uint32_t dst = sb +
                (uint32_t)(s * GEMM_STAGE + isB * 128 * ASTR + row * ASTR + c8) * 2u;
            cp16(dst, src);
        }
        CP_COMMIT();
    };

    float acc[2][8][4];
    #pragma unroll
    for (int mt = 0; mt < 2; mt++)
        #pragma unroll
        for (int nt = 0; nt < 8; nt++)
            #pragma unroll
            for (int r = 0; r < 4; r++) acc[mt][nt][r] = 0.f;

    load_stage(0, 0);
    for (int ks = 0; ks < NS; ks++) {
        const int s = ks & 1;
        if (ks + 1 < NS) { load_stage(1 - s, ks + 1); CP_WAIT(1); }
        else             { CP_WAIT(0); }
        __syncthreads();

        const uint32_t uA = sb + (uint32_t)(s * GEMM_STAGE) * 2u;
        const uint32_t uB = uA + (uint32_t)(128 * ASTR) * 2u;

        #pragma unroll
        for (int kk = 0; kk < 2; kk++) {
            const int kb = kk * 16;
            uint32_t a0[4], a1[4];
            const uint32_t aoff = (uint32_t)((wm0 + (lane & 15)) * ASTR + kb
                                             + ((lane & 16) ? 8 : 0)) * 2u;
            ldsm4(a0, uA + aoff);
            ldsm4(a1, uA + aoff + (uint32_t)(16 * ASTR) * 2u);
            #pragma unroll
            for (int np = 0; np < 4; np++) {
                const uint32_t boff = (uint32_t)((wn0 + np * 16 + (msel >> 1) * 8 + mrow) * ASTR
                                                 + kb + (msel & 1) * 8) * 2u;
                uint32_t b4[4];
                ldsm4(b4, uB + boff);
                mma_f16(acc[0][2 * np],     a0, b4 + 0);
                mma_f16(acc[0][2 * np + 1], a0, b4 + 2);
                mma_f16(acc[1][2 * np],     a1, b4 + 0);
                mma_f16(acc[1][2 * np + 1], a1, b4 + 2);
            }
        }
        __syncthreads();
    }

    // epilogue via fp32 smem staging
    float* Cs = reinterpret_cast<float*>(smh);
    #pragma unroll
    for (int mt = 0; mt < 2; mt++)
        #pragma unroll
        for (int nt = 0; nt < 8; nt++) {
            const int row = wm0 + mt * 16 + gid;
            const int col = wn0 + nt * 8 + t4 * 2;
            Cs[row * 132 + col]           = acc[mt][nt][0];
            Cs[row * 132 + col + 1]       = acc[mt][nt][1];
            Cs[(row + 8) * 132 + col]     = acc[mt][nt][2];
            Cs[(row + 8) * 132 + col + 1] = acc[mt][nt][3];
        }
    __syncthreads();
    #pragma unroll
    for (int it = 0; it < 16; it++) {
        const int id  = tid + it * 256;
        const int row = id >> 5;
        const int c4  = (id & 31) * 4;
        float4 v = *reinterpret_cast<const float4*>(&Cs[row * 132 + c4]);
        const int gc = bx * 128 + c4;
        v.x += bias[gc + 0]; v.y += bias[gc + 1]; v.z += bias[gc + 2]; v.w += bias[gc + 3];
        *reinterpret_cast<float4*>(&C[(size_t)(by * 128 + row) * N + gc]) = v;
    }
}

// ======================= RoPE + split-scatter ==============================
__global__ void rope_scatter(const float* __restrict__ qkv,
                             const float* __restrict__ freqs,
                             __half* __restrict__ Qh, __half* __restrict__ Ql,
                             __half* __restrict__ Kh, __half* __restrict__ Kl,
                             int S)
{
    const int s = blockIdx.x;
    const float* base = qkv + (size_t)s * (3 * D_MODEL);
    const float scale = 0.11180339887498949f;   // 1/sqrt(80)
    for (int idx = threadIdx.x; idx < NHEADS * HDIM; idx += blockDim.x) {
        const int h = idx / HDIM;
        const int d = idx % HDIM;
        const int dd = (d < 40) ? d : d - 40;
        const float f  = freqs[(size_t)s * 40 + dd];
        const float cs = cosf(f), sn = sinf(f);
        const float q1 = base[h * HDIM + dd];
        const float q2 = base[h * HDIM + dd + 40];
        const float k1 = base[D_MODEL + h * HDIM + dd];
        const float k2 = base[D_MODEL + h * HDIM + dd + 40];
        float qo = (d < 40) ? (q1 * cs - q2 * sn) : (q1 * sn + q2 * cs);
        const float ko = (d < 40) ? (k1 * cs - k2 * sn) : (k1 * sn + k2 * cs);
        qo *= scale;
        const size_t o = ((size_t)h * S + s) * HDIM + d;
        const __half qhi = __float2half_rn(qo);
        Qh[o] = qhi;
        Ql[o] = __float2half_rn(qo - __half2float(qhi));
        const __half khi = __float2half_rn(ko);
        Kh[o] = khi;
        Kl[o] = __float2half_rn(ko - __half2float(khi));
    }
}

// ======================= V transpose + split ===============================
__global__ void vtrans(const float* __restrict__ qkv,
                       __half* __restrict__ Vh, __half* __restrict__ Vl, int S)
{
    __shared__ float tile[64][84];
    const int tid = threadIdx.x;
    const int h  = blockIdx.y;
    const int s0 = blockIdx.x * 64;
    {
        const int sl = tid >> 2;
        const int dc = (tid & 3) * 20;
        const float* src = qkv + (size_t)(s0 + sl) * (3 * D_MODEL) + 2 * D_MODEL + h * HDIM + dc;
        #pragma unroll
        for (int i = 0; i < 5; i++) {
            float4 v = *reinterpret_cast<const float4*>(src + i * 4);
            tile[sl][dc + i * 4 + 0] = v.x;
            tile[sl][dc + i * 4 + 1] = v.y;
            tile[sl][dc + i * 4 + 2] = v.z;
            tile[sl][dc + i * 4 + 3] = v.w;
        }
    }
    __syncthreads();
    if (tid < 160) {
        const int d  = tid >> 1;
        const int sh = (tid & 1) * 32;
        const size_t o = ((size_t)(h * HDIM + d)) * S + s0 + sh;
        #pragma unroll
        for (int j = 0; j < 16; j++) {
            const float v0 = tile[sh + 2 * j][d];
            const float v1 = tile[sh + 2 * j + 1][d];
            const __half h0 = __float2half_rn(v0);
            const __half h1 = __float2half_rn(v1);
            __half2 hi; hi.x = h0; hi.y = h1;
            __half2 lo;
            lo.x = __float2half_rn(v0 - __half2float(h0));
            lo.y = __float2half_rn(v1 - __half2float(h1));
            *reinterpret_cast<__half2*>(&Vh[o + 2 * j]) = hi;
            *reinterpret_cast<__half2*>(&Vl[o + 2 * j]) = lo;
        }
    }
}

// ======================= fp16-split tensor-core attention ==================
// CTA = (q-tile 256, head), 16 warps x 16 q-rows, KV tile 64, 2-stage cp.async.
#define QSTR 88
#define VSTR 72
#define ATT_Q  (256 * QSTR)
#define ATT_K  (64 * QSTR)
#define ATT_V  (80 * VSTR)
#define ATC_SMEM ((2 * ATT_Q + 4 * ATT_K + 4 * ATT_V) * 2)   // 181248 B

__global__ __launch_bounds__(512)
void attn_tc(const __half* __restrict__ gQh, const __half* __restrict__ gQl,
             const __half* __restrict__ gKh, const __half* __restrict__ gKl,
             const __half* __restrict__ gVh, const __half* __restrict__ gVl,
             const int* __restrict__ cu, int n_seg,
             __half* __restrict__ outh, int S)
{
    extern __shared__ __half sh[];
    __half* Qh = sh;
    __half* Ql = Qh + ATT_Q;
    __half* Kh = Ql + ATT_Q;           // [2][ATT_K]
    __half* Kl = Kh + 2 * ATT_K;
    __half* Vh = Kl + 2 * ATT_K;       // [2][ATT_V]
    __half* Vl = Vh + 2 * ATT_V;

    const uint32_t uQh = smem_u32(Qh), uQl = smem_u32(Ql);
    const uint32_t uKh = smem_u32(Kh), uKl = smem_u32(Kl);
    const uint32_t uVh = smem_u32(Vh), uVl = smem_u32(Vl);

    const int tid  = threadIdx.x;
    const int warp = tid >> 5, lane = tid & 31;
    const int gid  = lane >> 2, t4 = lane & 3;
    const int mrow = lane & 7, msel = lane >> 3;
    const int wq   = warp * 16;
    const int h    = blockIdx.y;
    const int q0   = blockIdx.x * 256;

    int start = 0, end = S;
    for (int i = 0; i < n_seg; i++) {
        int a = cu[i], b = cu[i + 1];
        if (a <= q0 && q0 < b) { start = a; end = b; }
    }

    // ---- Q load (cp.async): 10 chunks/thread ----
    #pragma unroll
    for (int i = 0; i < 10; i++) {
        const int id  = tid + i * 512;        // 0..5119
        const int isL = id >= 2560;
        const int id2 = isL ? id - 2560 : id;
        const int r   = id2 / 10;
        const int c8  = (id2 % 10) * 8;
        const size_t so = ((size_t)h * S + q0 + r) * HDIM + c8;
        const uint32_t dst = (isL ? uQl : uQh) + (uint32_t)(r * QSTR + c8) * 2u;
        cp16(dst, (isL ? gQl : gQh) + so);
    }

    const int nkt = (end - start + 63) / 64;

    auto load_kv = [&](int st, int t) {
        const int k0 = start + t * 64;
        #pragma unroll
        for (int i = 0; i < 5; i++) {
            const int id = tid + i * 512;     // 0..2559
            if (id < 1280) {                  // K
                const int isL = id >= 640;
                const int id2 = isL ? id - 640 : id;
                const int r   = id2 / 10;
                const int c8  = (id2 % 10) * 8;
                const size_t so = ((size_t)h * S + k0 + r) * HDIM + c8;
                const uint32_t dst = (isL ? uKl : uKh) +
                    (uint32_t)(st * ATT_K + r * QSTR + c8) * 2u;
                cp16(dst, (isL ? gKl : gKh) + so);
            } else {                          // V
                const int idv = id - 1280;
                const int isL = idv >= 640;
                const int id2 = isL ? idv - 640 : idv;
                const int r   = id2 >> 3;
                const int c8  = (id2 & 7) * 8;
                const size_t so = ((size_t)(h * HDIM + r)) * S + k0 + c8;
                const uint32_t dst = (isL ? uVl : uVh) +
                    (uint32_t)(st * ATT_V + r * VSTR + c8) * 2u;
                cp16(dst, (isL ? gVl : gVh) + so);
            }
        }
    };

    load_kv(0, 0);
    CP_COMMIT();

    float acc_o[10][4];
    #pragma unroll
    for (int n = 0; n < 10; n++)
        #pragma unroll
        for (int r = 0; r < 4; r++) acc_o[n][r] = 0.f;
    float m0 = -INFINITY, m1 = -INFINITY, l0 = 0.f, l1 = 0.f;

    for (int t = 0; t < nkt; t++) {
        const int b = t & 1;
        if (t + 1 < nkt) { load_kv(1 - b, t + 1); CP_COMMIT(); CP_WAIT(1); }
        else             { CP_WAIT(0); }
        __syncthreads();

        const uint32_t kB = (uint32_t)(b * ATT_K) * 2u;
        const uint32_t vB = (uint32_t)(b * ATT_V) * 2u;

        // ---- QK^T: 5 k16-blocks, 3-MMA hi/lo split ----
        float acc_s[8][4];
        #pragma unroll
        for (int n = 0; n < 8; n++)
            #pragma unroll
            for (int r = 0; r < 4; r++) acc_s[n][r] = 0.f;

        #pragma unroll
        for (int kk = 0; kk < 5; kk++) {
            const int kb = kk * 16;
            uint32_t ah[4], al[4];
            {
                const uint32_t off = (uint32_t)((wq + (lane & 15)) * QSTR + kb
                                                + ((lane & 16) ? 8 : 0)) * 2u;
                ldsm4(ah, uQh + off);
                ldsm4(al, uQl + off);
            }
            #pragma unroll
            for (int np = 0; np < 4; np++) {
                const uint32_t off = (uint32_t)((np * 16 + (msel >> 1) * 8 + mrow) * QSTR
                                                + kb + (msel & 1) * 8) * 2u;
                uint32_t bh4[4], bl4[4];
                ldsm4(bh4, uKh + kB + off);
                ldsm4(bl4, uKl + kB + off);
                mma_f16(acc_s[2 * np],     ah, bh4 + 0);
                mma_f16(acc_s[2 * np],     al, bh4 + 0);
                mma_f16(acc_s[2 * np],     ah, bl4 + 0);
                mma_f16(acc_s[2 * np + 1], ah, bh4 + 2);
                mma_f16(acc_s[2 * np + 1], al, bh4 + 2);
                mma_f16(acc_s[2 * np + 1], ah, bl4 + 2);
            }
        }

        // ---- mask + online softmax ----
        const int k0 = start + t * 64;
        const int nv = end - k0;
        float mt0 = -INFINITY, mt1 = -INFINITY;
        #pragma unroll
        for (int nt = 0; nt < 8; nt++) {
            #pragma unroll
            for (int j = 0; j < 2; j++) {
                const int c = nt * 8 + 2 * t4 + j;
                if (c >= nv) { acc_s[nt][j] = -1e30f; acc_s[nt][2 + j] = -1e30f; }
                mt0 = fmaxf(mt0, acc_s[nt][j]);
                mt1 = fmaxf(mt1, acc_s[nt][2 + j]);
            }
        }
        mt0 = fmaxf(mt0, __shfl_xor_sync(0xffffffffu, mt0, 1));
        mt0 = fmaxf(mt0, __shfl_xor_sync(0xffffffffu, mt0, 2));
        mt1 = fmaxf(mt1, __shfl_xor_sync(0xffffffffu, mt1, 1));
        mt1 = fmaxf(mt1, __shfl_xor_sync(0xffffffffu, mt1, 2));

        const float mn0 = fmaxf(m0, mt0), mn1 = fmaxf(m1, mt1);
        const float al0 = __expf(m0 - mn0), al1 = __expf(m1 - mn1);
        m0 = mn0; m1 = mn1;

        float rs0 = 0.f, rs1 = 0.f;
        #pragma unroll
        for (int nt = 0; nt < 8; nt++) {
            #pragma unroll
            for (int j = 0; j < 2; j++) {
                const float p0 = __expf(acc_s[nt][j]     - m0);
                const float p1 = __expf(acc_s[nt][2 + j] - m1);
                acc_s[nt][j]     = p0;
                acc_s[nt][2 + j] = p1;
                rs0 += p0; rs1 += p1;
            }
        }
        rs0 += __shfl_xor_sync(0xffffffffu, rs0, 1);
        rs0 += __shfl_xor_sync(0xffffffffu, rs0, 2);
        rs1 += __shfl_xor_sync(0xffffffffu, rs1, 1);
        rs1 += __shfl_xor_sync(0xffffffffu, rs1, 2);
        l0 = l0 * al0 + rs0;
        l1 = l1 * al1 + rs1;

        #pragma unroll
        for (int n = 0; n < 10; n++) {
            acc_o[n][0] *= al0; acc_o[n][1] *= al0;
            acc_o[n][2] *= al1; acc_o[n][3] *= al1;
        }

        // ---- pack P into fp16 A-fragments ----
        uint32_t pk[4][4];
        #pragma unroll
        for (int kk = 0; kk < 4; kk++) {
            pk[kk][0] = pack_h2(acc_s[2 * kk][0],     acc_s[2 * kk][1]);
            pk[kk][1] = pack_h2(acc_s[2 * kk][2],     acc_s[2 * kk][3]);
            pk[kk][2] = pack_h2(acc_s[2 * kk + 1][0], acc_s[2 * kk + 1][1]);
            pk[kk][3] = pack_h2(acc_s[2 * kk + 1][2], acc_s[2 * kk + 1][3]);
        }

        // ---- PV: 4 k16-blocks, V-side hi/lo split ----
        #pragma unroll
        for (int kk = 0; kk < 4; kk++) {
            const int kb = kk * 16;
            #pragma unroll
            for (int vp = 0; vp < 5; vp++) {
                const uint32_t off = (uint32_t)((vp * 16 + (msel >> 1) * 8 + mrow) * VSTR
                                                + kb + (msel & 1) * 8) * 2u;
                uint32_t vh4[4], vl4[4];
                ldsm4(vh4, uVh + vB + off);
                ldsm4(vl4, uVl + vB + off);
                mma_f16(acc_o[2 * vp],     pk[kk], vh4 + 0);
                mma_f16(acc_o[2 * vp],     pk[kk], vl4 + 0);
                mma_f16(acc_o[2 * vp + 1], pk[kk], vh4 + 2);
                mma_f16(acc_o[2 * vp + 1], pk[kk], vl4 + 2);
            }
        }
        __syncthreads();
    }

    // ---- epilogue: write fp16 ----
    const float inv0 = 1.f / l0, inv1 = 1.f / l1;
    const int r0 = q0 + wq + gid, r1 = r0 + 8;
    #pragma unroll
    for (int nt = 0; nt < 10; nt++) {
        const int col = h * HDIM + nt * 8 + 2 * t4;
        __half2 v0 = __floats2half2_rn(acc_o[nt][0] * inv0, acc_o[nt][1] * inv0);
        __half2 v1 = __floats2half2_rn(acc_o[nt][2] * inv1, acc_o[nt][3] * inv1);
        *reinterpret_cast<__half2*>(&outh[(size_t)r0 * D_MODEL + col]) = v0;
        *reinterpret_cast<__half2*>(&outh[(size_t)r1 * D_MODEL + col]) = v1;
    }
}

// ======================= launch ============================================
extern "C" void kernel_launch(void* const* d_in, const int* in_sizes, int n_in,
                              void* d_out, int out_size)
{
    const float* hidden = (const float*)d_in[0];
    const int*   cu     = (const int*)  d_in[1];
    const float* rope   = (const float*)d_in[2];
    const float* w_qkv  = (const float*)d_in[3];
    const float* b_qkv  = (const float*)d_in[4];
    const float* w_proj = (const float*)d_in[5];
    const float* b_proj = (const float*)d_in[6];
    float* out = (float*)d_out;

    const int S     = in_sizes[0] / D_MODEL;
    const int n_seg = in_sizes[1] - 1;

    float *qkv_p;
    __half *hh, *attnh, *wqh, *wph, *qh, *ql, *kh, *kl, *vh, *vl;
    cudaGetSymbolAddress((void**)&qkv_p, g_qkv);
    cudaGetSymbolAddress((void**)&hh,    g_hh);
    cudaGetSymbolAddress((void**)&attnh, g_attnh);
    cudaGetSymbolAddress((void**)&wqh,   g_wqkv_h);
    cudaGetSymbolAddress((void**)&wph,   g_wproj_h);
    cudaGetSymbolAddress((void**)&qh, g_qh);
    cudaGetSymbolAddress((void**)&ql, g_ql);
    cudaGetSymbolAddress((void**)&kh, g_kh);
    cudaGetSymbolAddress((void**)&kl, g_kl);
    cudaGetSymbolAddress((void**)&vh, g_vh);
    cudaGetSymbolAddress((void**)&vl, g_vl);

    cudaFuncSetAttribute(gemm_f16, cudaFuncAttributeMaxDynamicSharedMemorySize, GEMM_SMEM);
    cudaFuncSetAttribute(attn_tc,  cudaFuncAttributeMaxDynamicSharedMemorySize, ATC_SMEM);

    // 0) weight transpose -> fp16; hidden -> fp16
    {
        dim3 blk(32, 8);
        wtrans16<<<dim3(3 * D_MODEL / 32, D_MODEL / 32), blk>>>(w_qkv, wqh, D_MODEL, 3 * D_MODEL);
        wtrans16<<<dim3(D_MODEL / 32, D_MODEL / 32), blk>>>(w_proj, wph, D_MODEL, D_MODEL);
        f2h<<<(S * D_MODEL) / (256 * 4), 256>>>(hidden, hh);
    }

    // 1) QKV projection (plain fp16)
    gemm_f16<<<dim3(3 * D_MODEL / 128, S / 128), 256, GEMM_SMEM>>>(
        hh, wqh, b_qkv, qkv_p, S, 3 * D_MODEL, D_MODEL);

    // 2) RoPE + hi/lo split scatter; V transpose + split
    rope_scatter<<<S, 256>>>(qkv_p, rope, qh, ql, kh, kl, S);
    vtrans<<<dim3(S / 64, NHEADS), 256>>>(qkv_p, vh, vl, S);

    // 3) block-diagonal attention (fp16-split tensor cores), fp16 output
    attn_tc<<<dim3(S / 256, NHEADS), 512, ATC_SMEM>>>(
        qh, ql, kh, kl, vh, vl, cu, n_seg, attnh, S);

    // 4) output projection (plain fp16)
    gemm_f16<<<dim3(D_MODEL / 128, S / 128), 256, GEMM_SMEM>>>(
        attnh, wph, b_proj, out, S, D_MODEL, D_MODEL);
}